// round 8
// baseline (speedup 1.0000x reference)
#include <cuda_runtime.h>
#include <cstddef>

// ---------------------------------------------------------------------------
// Problem constants (fixed by the dataset)
// ---------------------------------------------------------------------------
#define S_LEN 2048
#define BATCH 64
#define IN0   64
#define HID   128
#define GDIM  512          // 4*HID, PyTorch gate order: i, f, g, o
#define NL    6
#define MROWS (BATCH * S_LEN)   // 131072

// ---------------------------------------------------------------------------
// Static device scratch (no allocation allowed)
// ---------------------------------------------------------------------------
__device__ float g_xg  [(size_t)MROWS * GDIM];  // 256 MB: per-layer xg = seq @ Wih^T
__device__ float g_seq0[(size_t)MROWS * HID];   // 64 MB ping
__device__ float g_seq1[(size_t)MROWS * HID];   // 64 MB pong

typedef unsigned long long u64;

// ---------------------------------------------------------------------------
// f32x2 helpers (sm_103a packed fp32 pipe)
// ---------------------------------------------------------------------------
__device__ __forceinline__ u64 pk2(float a, float b) {
    u64 r;
    unsigned ua = __float_as_uint(a), ub = __float_as_uint(b);
    asm("mov.b64 %0, {%1, %2};" : "=l"(r) : "r"(ua), "r"(ub));
    return r;
}
__device__ __forceinline__ u64 ffma2(u64 a, u64 b, u64 c) {
    u64 d;
    asm("fma.rn.f32x2 %0, %1, %2, %3;" : "=l"(d) : "l"(a), "l"(b), "l"(c));
    return d;
}
__device__ __forceinline__ float2 upk2(u64 v) {
    unsigned lo, hi;
    asm("mov.b64 {%0, %1}, %2;" : "=r"(lo), "=r"(hi) : "l"(v));
    return make_float2(__uint_as_float(lo), __uint_as_float(hi));
}

__device__ __forceinline__ float sigf(float x)   { return 1.0f / (1.0f + __expf(-x)); }
__device__ __forceinline__ float tanh_f(float x) { return 2.0f * sigf(2.0f * x) - 1.0f; }

__device__ __forceinline__ unsigned sptr(const void* p) {
    return (unsigned)__cvta_generic_to_shared(p);
}

// ---------------------------------------------------------------------------
// GEMM: g_xg[r][n] = sum_k A[r][k] * W[n][k]   (unchanged from round 6)
// ---------------------------------------------------------------------------
template<int K>
__global__ __launch_bounds__(256, 1)
void gemm_xg(const float* __restrict__ Ax, const float* __restrict__ W, int asel)
{
    const float* A = (asel == 1) ? g_seq0 : (asel == 2) ? g_seq1 : Ax;
    extern __shared__ float sm[];
    float* As = sm;             // 128 x 68
    float* Bs = sm + 128 * 68;  // 128 x 68
    const int tx = threadIdx.x & 15;
    const int ty = threadIdx.x >> 4;
    const int row0 = blockIdx.y * 128;
    const int col0 = blockIdx.x * 128;

    u64 acc2[8][8];
#pragma unroll
    for (int i = 0; i < 8; i++)
#pragma unroll
        for (int j = 0; j < 8; j++) acc2[i][j] = 0ull;

    const int NCH = K / 64;
    for (int kc = 0; kc < NCH; kc++) {
        if (kc) __syncthreads();
#pragma unroll
        for (int p = 0; p < 8; p++) {
            int idx = threadIdx.x + 256 * p;
            int r = idx >> 4;
            int q = idx & 15;
            float4 av = *(const float4*)(A + (size_t)(row0 + r) * K + kc * 64 + 4 * q);
            *(float4*)(As + r * 68 + 4 * q) = av;
            float4 wv = *(const float4*)(W + (size_t)(col0 + r) * K + kc * 64 + 4 * q);
            *(float4*)(Bs + r * 68 + 4 * q) = wv;
        }
        __syncthreads();

        const ulonglong2* As2 = (const ulonglong2*)As;
        const ulonglong2* Bs2 = (const ulonglong2*)Bs;
        for (int kq = 0; kq < 16; kq++) {
            ulonglong2 b2[8];
#pragma unroll
            for (int j = 0; j < 8; j++) b2[j] = Bs2[(tx + 16 * j) * 17 + kq];
#pragma unroll
            for (int i = 0; i < 8; i++) {
                ulonglong2 a2 = As2[(ty + 16 * i) * 17 + kq];
#pragma unroll
                for (int j = 0; j < 8; j++) {
                    acc2[i][j] = ffma2(a2.x, b2[j].x, acc2[i][j]);
                    acc2[i][j] = ffma2(a2.y, b2[j].y, acc2[i][j]);
                }
            }
        }
    }

#pragma unroll
    for (int i = 0; i < 8; i++) {
        size_t rbase = (size_t)(row0 + ty + 16 * i) * GDIM + col0 + tx;
#pragma unroll
        for (int j = 0; j < 8; j++) {
            float2 p = upk2(acc2[i][j]);
            g_xg[rbase + 16 * j] = p.x + p.y;
        }
    }
}

// ---------------------------------------------------------------------------
// Recurrent kernel, shuffle + split-matvec cluster version.
//   2 CTAs per batch row (cluster (2,1,1)); rank r owns h[64r, 64r+64).
//   Warp w, lane l: hh = w*8 + (l&7), gt = l>>3 (i,f,g,o). Full Whh row per
//   thread in 64 u64 regs. Gates gathered via 3 shfl (no SMEM, no bar.sync).
//   Cell update runs on lanes 0-7 of EVERY warp. Two mbarriers:
//   mb_local (64 local release.cta arrives/step) and mb_peer (64 peer
//   release.cluster arrives/step). Matvec split local/remote so the peer's
//   DSMEM h store latency hides behind the local-half FMA chain.
//   Phase map: prologue completes phase 0; step t completes phase t+1.
//   POST-LOOP DRAIN (the round-7 crash fix): every thread waits phase 2048
//   (parity 0) on BOTH barriers, then barrier.cluster — no CTA exits while
//   the peer's final st.shared::cluster/arrive is still in flight.
// ---------------------------------------------------------------------------
__global__ __launch_bounds__(256, 1) __cluster_dims__(2, 1, 1)
void lstm_recur2(const float* __restrict__ Whh,   // (512,128) this layer
                 const float* __restrict__ h0,    // (64,128)
                 const float* __restrict__ c0,    // (64,128)
                 const float* __restrict__ bih,   // (512)
                 const float* __restrict__ bhh,   // (512)
                 int osel,                        // 1 -> g_seq0, 2 -> g_seq1
                 float* __restrict__ hT)          // (64,128) slice of output
{
    __shared__ alignas(16) float sH[2][HID];   // double-buffered hidden state
    __shared__ alignas(8) u64 mb_local;        // 64 local updater arrives/step
    __shared__ alignas(8) u64 mb_peer;         // 64 peer updater arrives/step

    const int tid = threadIdx.x;
    const int l   = tid & 31;
    const int w   = tid >> 5;
    unsigned rank;
    asm("mov.u32 %0, %%cluster_ctarank;" : "=r"(rank));
    const int r = (int)rank;                   // 0 or 1
    const int b = blockIdx.x >> 1;             // batch row
    const int gt = l >> 3;                     // gate: 0=i 1=f 2=g 3=o
    const int hh = w * 8 + (l & 7);            // h sub-index 0..63
    const int grow = gt * HID + r * 64 + hh;   // global gate row
    const int hidx = r * 64 + hh;
    const bool upd = (l < 8);                  // i-lanes do the cell update
    float* seq_out = (osel == 1) ? g_seq0 : g_seq1;

    // ---- peer addresses ----
    const unsigned peer = rank ^ 1u;
    unsigned lsh0 = sptr(&sH[0][0]);
    unsigned lsh1 = sptr(&sH[1][0]);
    unsigned lmbl = sptr(&mb_local);
    unsigned lmbp = sptr(&mb_peer);
    unsigned psh0, psh1, pmbp;
    asm("mapa.shared::cluster.u32 %0, %1, %2;" : "=r"(psh0) : "r"(lsh0), "r"(peer));
    asm("mapa.shared::cluster.u32 %0, %1, %2;" : "=r"(psh1) : "r"(lsh1), "r"(peer));
    asm("mapa.shared::cluster.u32 %0, %1, %2;" : "=r"(pmbp) : "r"(lmbp), "r"(peer));

    // ---- full Whh row into 64 u64 registers (pair q = k{2q,2q+1}) ----
    u64 w2[64];
    {
        const float* wrow = Whh + (size_t)grow * HID;
#pragma unroll
        for (int q = 0; q < 32; q++) {
            float4 v = *(const float4*)(wrow + 4 * q);
            w2[2 * q]     = pk2(v.x, v.y);
            w2[2 * q + 1] = pk2(v.z, v.w);
        }
    }
    const float biasg = bih[grow] + bhh[grow];
    const int lb = 32 * r;        // u64 base of local h half
    const int rb = 32 * (1 - r);  // u64 base of remote h half

    // ---- init ----
    if (tid < HID) sH[1][tid] = h0[b * HID + tid];
    float c = 0.0f, hlast = 0.0f;
    if (upd) c = c0[b * HID + hidx];
    if (tid == 0) {
        asm volatile("mbarrier.init.shared.b64 [%0], 64;" :: "r"(lmbl) : "memory");
        asm volatile("mbarrier.init.shared.b64 [%0], 64;" :: "r"(lmbp) : "memory");
    }
    __syncthreads();
    asm volatile("barrier.cluster.arrive.aligned;" ::: "memory");
    asm volatile("barrier.cluster.wait.aligned;"   ::: "memory");
    // prologue arrives: complete phase 0 so the t=0 waits pass immediately
    if (upd) {
        asm volatile("mbarrier.arrive.release.cta.shared::cta.b64 _, [%0];"
                     :: "r"(lmbl) : "memory");
        asm volatile("mbarrier.arrive.release.cluster.shared::cluster.b64 _, [%0];"
                     :: "r"(pmbp) : "memory");
    }

    const float* xrow = g_xg + ((size_t)b * S_LEN) * GDIM + grow;
    float* orow = seq_out + ((size_t)b * S_LEN) * HID;

    float xcur = xrow[0];
    for (int t = 0; t < S_LEN; t++) {
        float xnext = (t + 1 < S_LEN) ? xrow[(size_t)(t + 1) * GDIM] : 0.0f;
        const u64* h2 = (const u64*)sH[(t + 1) & 1];
        const unsigned par = (unsigned)(t & 1);

        // ---- wait local h half (fast: local arrives) ----
        asm volatile(
            "{\n\t.reg .pred P;\n\t"
            "WA_%=:\n\t"
            "mbarrier.try_wait.parity.acquire.cta.shared::cta.b64 P, [%0], %1, 0x989680;\n\t"
            "@!P bra WA_%=;\n\t}"
            :: "r"(lmbl), "r"(par) : "memory");

        // ---- local-half matvec (hides the peer's DSMEM store latency) ----
        u64 a0 = pk2(xcur + biasg, 0.0f);
        u64 a1 = 0ull, a2 = 0ull, a3 = 0ull;
#pragma unroll
        for (int q = 0; q < 8; q++) {
            a0 = ffma2(w2[lb + 4 * q + 0], h2[lb + 4 * q + 0], a0);
            a1 = ffma2(w2[lb + 4 * q + 1], h2[lb + 4 * q + 1], a1);
            a2 = ffma2(w2[lb + 4 * q + 2], h2[lb + 4 * q + 2], a2);
            a3 = ffma2(w2[lb + 4 * q + 3], h2[lb + 4 * q + 3], a3);
        }

        // ---- wait peer h half ----
        asm volatile(
            "{\n\t.reg .pred P;\n\t"
            "WB_%=:\n\t"
            "mbarrier.try_wait.parity.acquire.cluster.shared::cta.b64 P, [%0], %1, 0x989680;\n\t"
            "@!P bra WB_%=;\n\t}"
            :: "r"(lmbp), "r"(par) : "memory");

        // ---- remote-half matvec ----
#pragma unroll
        for (int q = 0; q < 8; q++) {
            a0 = ffma2(w2[rb + 4 * q + 0], h2[rb + 4 * q + 0], a0);
            a1 = ffma2(w2[rb + 4 * q + 1], h2[rb + 4 * q + 1], a1);
            a2 = ffma2(w2[rb + 4 * q + 2], h2[rb + 4 * q + 2], a2);
            a3 = ffma2(w2[rb + 4 * q + 3], h2[rb + 4 * q + 3], a3);
        }
        float2 p0 = upk2(a0), p1 = upk2(a1), p2 = upk2(a2), p3 = upk2(a3);
        float raw = ((p0.x + p0.y) + (p1.x + p1.y)) + ((p2.x + p2.y) + (p3.x + p3.y));

        // ---- activation (uniform code, no divergence) ----
        float xx = (gt == 2) ? 2.0f * raw : raw;
        float s  = sigf(xx);
        float act = (gt == 2) ? (2.0f * s - 1.0f) : s;

        // ---- gather f,g,o into the i-lanes via shuffles ----
        const int base = l & 7;
        float fv = __shfl_sync(0xffffffffu, act, base + 8);
        float gv = __shfl_sync(0xffffffffu, act, base + 16);
        float ov = __shfl_sync(0xffffffffu, act, base + 24);

        // ---- cell/hidden update on lanes 0-7 of every warp ----
        if (upd) {
            float iv = act;
            c = fv * c + iv * gv;
            float h = ov * tanh_f(c);
            hlast = h;
            const int wbuf = t & 1;
            sH[wbuf][hidx] = h;                               // local copy
            asm volatile("mbarrier.arrive.release.cta.shared::cta.b64 _, [%0];"
                         :: "r"(lmbl) : "memory");
            unsigned pdst = ((wbuf == 0) ? psh0 : psh1) + 4u * (unsigned)hidx;
            asm volatile("st.shared::cluster.f32 [%0], %1;" :: "r"(pdst), "f"(h) : "memory");
            asm volatile("mbarrier.arrive.release.cluster.shared::cluster.b64 _, [%0];"
                         :: "r"(pmbp) : "memory");
            orow[(size_t)t * HID + hidx] = h;                 // sequence output
        }
        xcur = xnext;
    }

    // ---- post-loop drain: consume step-2047 arrives (phase 2048, parity 0)
    //      on BOTH barriers so no remote store/arrive targets this CTA's
    //      SMEM after it exits. Then a final cluster barrier.
    asm volatile(
        "{\n\t.reg .pred P;\n\t"
        "WD_%=:\n\t"
        "mbarrier.try_wait.parity.acquire.cta.shared::cta.b64 P, [%0], 0, 0x989680;\n\t"
        "@!P bra WD_%=;\n\t}"
        :: "r"(lmbl) : "memory");
    asm volatile(
        "{\n\t.reg .pred P;\n\t"
        "WE_%=:\n\t"
        "mbarrier.try_wait.parity.acquire.cluster.shared::cta.b64 P, [%0], 0, 0x989680;\n\t"
        "@!P bra WE_%=;\n\t}"
        :: "r"(lmbp) : "memory");
    asm volatile("barrier.cluster.arrive.aligned;" ::: "memory");
    asm volatile("barrier.cluster.wait.aligned;"   ::: "memory");

    if (upd) hT[b * HID + hidx] = hlast;
}

// ---------------------------------------------------------------------------
// Launch: per layer, GEMM (xg precompute) then recurrent scan.
// ---------------------------------------------------------------------------
extern "C" void kernel_launch(void* const* d_in, const int* in_sizes, int n_in,
                              void* d_out, int out_size)
{
    const float* x    = (const float*)d_in[0];  // (64,2048,64)
    const float* h0   = (const float*)d_in[1];  // (6,64,128)
    const float* c0   = (const float*)d_in[2];  // (6,64,128)
    const float* Wih0 = (const float*)d_in[3];  // (512,64)
    const float* WihR = (const float*)d_in[4];  // (5,512,128)
    const float* Whh  = (const float*)d_in[5];  // (6,512,128)
    const float* bih  = (const float*)d_in[6];  // (6,512)
    const float* bhh  = (const float*)d_in[7];  // (6,512)
    float* out = (float*)d_out;                 // (6,64,128)

    const int GEMM_SMEM = 2 * 128 * 68 * 4;     // 69,632 B
    cudaFuncSetAttribute(gemm_xg<64>,  cudaFuncAttributeMaxDynamicSharedMemorySize, GEMM_SMEM);
    cudaFuncSetAttribute(gemm_xg<128>, cudaFuncAttributeMaxDynamicSharedMemorySize, GEMM_SMEM);

    dim3 ggrid(4, 1024);   // N-tiles x M-tiles

    // layer 0: input x (K=64), recur writes g_seq0 (osel=1)
    gemm_xg<64><<<ggrid, 256, GEMM_SMEM>>>(x, Wih0, 0);
    lstm_recur2<<<2 * BATCH, 256>>>(Whh, h0, c0, bih, bhh, 1, out);

    int insel = 1;
    for (int l = 1; l < NL; l++) {
        int outsel = (insel == 1) ? 2 : 1;
        gemm_xg<128><<<ggrid, 256, GEMM_SMEM>>>(
            nullptr, WihR + (size_t)(l - 1) * GDIM * HID, insel);
        lstm_recur2<<<2 * BATCH, 256>>>(
            Whh + (size_t)l * GDIM * HID,
            h0 + l * BATCH * HID,
            c0 + l * BATCH * HID,
            bih + l * GDIM,
            bhh + l * GDIM,
            outsel,
            out + l * BATCH * HID);
        insel = outsel;
    }
}

// round 9
// speedup vs baseline: 1.0911x; 1.0911x over previous
#include <cuda_runtime.h>
#include <cstddef>

// ---------------------------------------------------------------------------
// Problem constants (fixed by the dataset)
// ---------------------------------------------------------------------------
#define S_LEN 2048
#define BATCH 64
#define IN0   64
#define HID   128
#define GDIM  512          // 4*HID, PyTorch gate order: i, f, g, o
#define NL    6
#define MROWS (BATCH * S_LEN)   // 131072

// ---------------------------------------------------------------------------
// Static device scratch (no allocation allowed)
// ---------------------------------------------------------------------------
__device__ float g_xg  [(size_t)MROWS * GDIM];  // 256 MB: per-layer xg = seq @ Wih^T
__device__ float g_seq0[(size_t)MROWS * HID];   // 64 MB ping
__device__ float g_seq1[(size_t)MROWS * HID];   // 64 MB pong

typedef unsigned long long u64;

// ---------------------------------------------------------------------------
// f32x2 helpers (sm_103a packed fp32 pipe)
// ---------------------------------------------------------------------------
__device__ __forceinline__ u64 pk2(float a, float b) {
    u64 r;
    unsigned ua = __float_as_uint(a), ub = __float_as_uint(b);
    asm("mov.b64 %0, {%1, %2};" : "=l"(r) : "r"(ua), "r"(ub));
    return r;
}
__device__ __forceinline__ u64 ffma2(u64 a, u64 b, u64 c) {
    u64 d;
    asm("fma.rn.f32x2 %0, %1, %2, %3;" : "=l"(d) : "l"(a), "l"(b), "l"(c));
    return d;
}
__device__ __forceinline__ float2 upk2(u64 v) {
    unsigned lo, hi;
    asm("mov.b64 {%0, %1}, %2;" : "=r"(lo), "=r"(hi) : "l"(v));
    return make_float2(__uint_as_float(lo), __uint_as_float(hi));
}

__device__ __forceinline__ float sigf(float x)   { return 1.0f / (1.0f + __expf(-x)); }
__device__ __forceinline__ float tanh_f(float x) { return 2.0f * sigf(2.0f * x) - 1.0f; }

__device__ __forceinline__ unsigned sptr(const void* p) {
    return (unsigned)__cvta_generic_to_shared(p);
}

// ---------------------------------------------------------------------------
// GEMM: g_xg[r][n] = sum_k A[r][k] * W[n][k]   (unchanged from round 6)
// ---------------------------------------------------------------------------
template<int K>
__global__ __launch_bounds__(256, 1)
void gemm_xg(const float* __restrict__ Ax, const float* __restrict__ W, int asel)
{
    const float* A = (asel == 1) ? g_seq0 : (asel == 2) ? g_seq1 : Ax;
    extern __shared__ float sm[];
    float* As = sm;             // 128 x 68
    float* Bs = sm + 128 * 68;  // 128 x 68
    const int tx = threadIdx.x & 15;
    const int ty = threadIdx.x >> 4;
    const int row0 = blockIdx.y * 128;
    const int col0 = blockIdx.x * 128;

    u64 acc2[8][8];
#pragma unroll
    for (int i = 0; i < 8; i++)
#pragma unroll
        for (int j = 0; j < 8; j++) acc2[i][j] = 0ull;

    const int NCH = K / 64;
    for (int kc = 0; kc < NCH; kc++) {
        if (kc) __syncthreads();
#pragma unroll
        for (int p = 0; p < 8; p++) {
            int idx = threadIdx.x + 256 * p;
            int r = idx >> 4;
            int q = idx & 15;
            float4 av = *(const float4*)(A + (size_t)(row0 + r) * K + kc * 64 + 4 * q);
            *(float4*)(As + r * 68 + 4 * q) = av;
            float4 wv = *(const float4*)(W + (size_t)(col0 + r) * K + kc * 64 + 4 * q);
            *(float4*)(Bs + r * 68 + 4 * q) = wv;
        }
        __syncthreads();

        const ulonglong2* As2 = (const ulonglong2*)As;
        const ulonglong2* Bs2 = (const ulonglong2*)Bs;
        for (int kq = 0; kq < 16; kq++) {
            ulonglong2 b2[8];
#pragma unroll
            for (int j = 0; j < 8; j++) b2[j] = Bs2[(tx + 16 * j) * 17 + kq];
#pragma unroll
            for (int i = 0; i < 8; i++) {
                ulonglong2 a2 = As2[(ty + 16 * i) * 17 + kq];
#pragma unroll
                for (int j = 0; j < 8; j++) {
                    acc2[i][j] = ffma2(a2.x, b2[j].x, acc2[i][j]);
                    acc2[i][j] = ffma2(a2.y, b2[j].y, acc2[i][j]);
                }
            }
        }
    }

#pragma unroll
    for (int i = 0; i < 8; i++) {
        size_t rbase = (size_t)(row0 + ty + 16 * i) * GDIM + col0 + tx;
#pragma unroll
        for (int j = 0; j < 8; j++) {
            float2 p = upk2(acc2[i][j]);
            g_xg[rbase + 16 * j] = p.x + p.y;
        }
    }
}

// ---------------------------------------------------------------------------
// Recurrent kernel: cluster (2,1,1), minimal-sync protocol.
//   2 CTAs per batch row; rank r owns h[64r, 64r+64). Warp w lane l:
//   hh = w*8 + (l&7), gt = l>>3. Full Whh row per thread in 64 u64 regs.
//   Gates gathered via 3 shfl. Cell update on lanes 0-7 of every warp.
//   SYNC (the round-8 fix): ONE mbarrier (mb_peer, count 8 = one lane-0
//   arrive per peer warp) for the cross-CTA h exchange; local cross-warp
//   visibility via the single end-of-step __syncthreads(). No per-lane
//   arrives, no local mbarrier, no double spin.
//   Matvec split local/remote around the single wait so the DSMEM fabric
//   latency hides behind the local-half FMA chain.
//   Phase map: prologue completes phase 0; step t's arrives complete
//   phase t+1; step t waits parity t&1 (phase t). Post-loop drain waits
//   phase 2048 (parity 0) + cluster barrier so no CTA exits with peer
//   traffic in flight.
// ---------------------------------------------------------------------------
__global__ __launch_bounds__(256, 1) __cluster_dims__(2, 1, 1)
void lstm_recur2(const float* __restrict__ Whh,   // (512,128) this layer
                 const float* __restrict__ h0,    // (64,128)
                 const float* __restrict__ c0,    // (64,128)
                 const float* __restrict__ bih,   // (512)
                 const float* __restrict__ bhh,   // (512)
                 int osel,                        // 1 -> g_seq0, 2 -> g_seq1
                 float* __restrict__ hT)          // (64,128) slice of output
{
    __shared__ alignas(16) float sH[2][HID];   // double-buffered hidden state
    __shared__ alignas(8) u64 mb_peer;         // 8 peer warp-arrives per step

    const int tid = threadIdx.x;
    const int l   = tid & 31;
    const int w   = tid >> 5;
    unsigned rank;
    asm("mov.u32 %0, %%cluster_ctarank;" : "=r"(rank));
    const int r = (int)rank;                   // 0 or 1
    const int b = blockIdx.x >> 1;             // batch row
    const int gt = l >> 3;                     // gate: 0=i 1=f 2=g 3=o
    const int hh = w * 8 + (l & 7);            // h sub-index 0..63
    const int grow = gt * HID + r * 64 + hh;   // global gate row
    const int hidx = r * 64 + hh;
    const bool upd = (l < 8);                  // i-lanes do the cell update
    float* seq_out = (osel == 1) ? g_seq0 : g_seq1;

    // ---- peer addresses ----
    const unsigned peer = rank ^ 1u;
    unsigned lsh0 = sptr(&sH[0][0]);
    unsigned lsh1 = sptr(&sH[1][0]);
    unsigned lmbp = sptr(&mb_peer);
    unsigned psh0, psh1, pmbp;
    asm("mapa.shared::cluster.u32 %0, %1, %2;" : "=r"(psh0) : "r"(lsh0), "r"(peer));
    asm("mapa.shared::cluster.u32 %0, %1, %2;" : "=r"(psh1) : "r"(lsh1), "r"(peer));
    asm("mapa.shared::cluster.u32 %0, %1, %2;" : "=r"(pmbp) : "r"(lmbp), "r"(peer));

    // ---- full Whh row into 64 u64 registers (pair q = k{2q,2q+1}) ----
    u64 w2[64];
    {
        const float* wrow = Whh + (size_t)grow * HID;
#pragma unroll
        for (int q = 0; q < 32; q++) {
            float4 v = *(const float4*)(wrow + 4 * q);
            w2[2 * q]     = pk2(v.x, v.y);
            w2[2 * q + 1] = pk2(v.z, v.w);
        }
    }
    const float biasg = bih[grow] + bhh[grow];
    const int lb = 32 * r;        // u64 base of local h half
    const int rb = 32 * (1 - r);  // u64 base of remote h half

    // ---- init ----
    if (tid < HID) sH[1][tid] = h0[b * HID + tid];
    float c = 0.0f, hlast = 0.0f;
    if (upd) c = c0[b * HID + hidx];
    if (tid == 0) {
        asm volatile("mbarrier.init.shared.b64 [%0], 8;" :: "r"(lmbp) : "memory");
    }
    __syncthreads();
    asm volatile("barrier.cluster.arrive.aligned;" ::: "memory");
    asm volatile("barrier.cluster.wait.aligned;"   ::: "memory");
    // prologue: one arrive per warp on the PEER's barrier -> completes phase 0
    if (l == 0) {
        asm volatile("mbarrier.arrive.release.cluster.shared::cluster.b64 _, [%0];"
                     :: "r"(pmbp) : "memory");
    }

    const float* xrow = g_xg + ((size_t)b * S_LEN) * GDIM + grow;
    float* orow = seq_out + ((size_t)b * S_LEN) * HID;

    float xcur = xrow[0];
    for (int t = 0; t < S_LEN; t++) {
        float xnext = (t + 1 < S_LEN) ? xrow[(size_t)(t + 1) * GDIM] : 0.0f;
        const u64* h2 = (const u64*)sH[(t + 1) & 1];
        const unsigned par = (unsigned)(t & 1);

        // ---- local-half matvec (local h visible via last step's bar.sync;
        //      runs while the peer's DSMEM store/arrive is in flight) ----
        u64 a0 = pk2(xcur + biasg, 0.0f);
        u64 a1 = 0ull, a2 = 0ull, a3 = 0ull;
#pragma unroll
        for (int q = 0; q < 8; q++) {
            a0 = ffma2(w2[lb + 4 * q + 0], h2[lb + 4 * q + 0], a0);
            a1 = ffma2(w2[lb + 4 * q + 1], h2[lb + 4 * q + 1], a1);
            a2 = ffma2(w2[lb + 4 * q + 2], h2[lb + 4 * q + 2], a2);
            a3 = ffma2(w2[lb + 4 * q + 3], h2[lb + 4 * q + 3], a3);
        }

        // ---- single wait: peer h half for this step ----
        asm volatile(
            "{\n\t.reg .pred P;\n\t"
            "WB_%=:\n\t"
            "mbarrier.try_wait.parity.acquire.cluster.shared::cta.b64 P, [%0], %1, 0x989680;\n\t"
            "@!P bra WB_%=;\n\t}"
            :: "r"(lmbp), "r"(par) : "memory");

        // ---- remote-half matvec ----
#pragma unroll
        for (int q = 0; q < 8; q++) {
            a0 = ffma2(w2[rb + 4 * q + 0], h2[rb + 4 * q + 0], a0);
            a1 = ffma2(w2[rb + 4 * q + 1], h2[rb + 4 * q + 1], a1);
            a2 = ffma2(w2[rb + 4 * q + 2], h2[rb + 4 * q + 2], a2);
            a3 = ffma2(w2[rb + 4 * q + 3], h2[rb + 4 * q + 3], a3);
        }
        float2 p0 = upk2(a0), p1 = upk2(a1), p2 = upk2(a2), p3 = upk2(a3);
        float raw = ((p0.x + p0.y) + (p1.x + p1.y)) + ((p2.x + p2.y) + (p3.x + p3.y));

        // ---- activation (uniform code, no divergence) ----
        float xx = (gt == 2) ? 2.0f * raw : raw;
        float s  = sigf(xx);
        float act = (gt == 2) ? (2.0f * s - 1.0f) : s;

        // ---- gather f,g,o into the i-lanes via shuffles (independent) ----
        const int base = l & 7;
        float fv = __shfl_sync(0xffffffffu, act, base + 8);
        float gv = __shfl_sync(0xffffffffu, act, base + 16);
        float ov = __shfl_sync(0xffffffffu, act, base + 24);

        // ---- cell/hidden update on lanes 0-7 of every warp ----
        const int wbuf = t & 1;
        if (upd) {
            float iv = act;
            c = fv * c + iv * gv;
            float h = ov * tanh_f(c);
            hlast = h;
            // remote store FIRST (peer needs it soonest)
            unsigned pdst = ((wbuf == 0) ? psh0 : psh1) + 4u * (unsigned)hidx;
            asm volatile("st.shared::cluster.f32 [%0], %1;" :: "r"(pdst), "f"(h) : "memory");
            sH[wbuf][hidx] = h;                               // local copy
            orow[(size_t)t * HID + hidx] = h;                 // sequence output
        }
        __syncwarp();
        // one arrive per warp; release covers the warp's DSMEM stores
        if (l == 0) {
            asm volatile("mbarrier.arrive.release.cluster.shared::cluster.b64 _, [%0];"
                         :: "r"(pmbp) : "memory");
        }
        __syncthreads();   // local h visibility for next step's local half
        xcur = xnext;
    }

    // ---- drain: consume step-2047 arrives (phase 2048, parity 0), then a
    //      final cluster barrier so no remote traffic outlives this CTA.
    asm volatile(
        "{\n\t.reg .pred P;\n\t"
        "WD_%=:\n\t"
        "mbarrier.try_wait.parity.acquire.cluster.shared::cta.b64 P, [%0], 0, 0x989680;\n\t"
        "@!P bra WD_%=;\n\t}"
        :: "r"(lmbp) : "memory");
    asm volatile("barrier.cluster.arrive.aligned;" ::: "memory");
    asm volatile("barrier.cluster.wait.aligned;"   ::: "memory");

    if (upd) hT[b * HID + hidx] = hlast;
}

// ---------------------------------------------------------------------------
// Launch: per layer, GEMM (xg precompute) then recurrent scan.
// ---------------------------------------------------------------------------
extern "C" void kernel_launch(void* const* d_in, const int* in_sizes, int n_in,
                              void* d_out, int out_size)
{
    const float* x    = (const float*)d_in[0];  // (64,2048,64)
    const float* h0   = (const float*)d_in[1];  // (6,64,128)
    const float* c0   = (const float*)d_in[2];  // (6,64,128)
    const float* Wih0 = (const float*)d_in[3];  // (512,64)
    const float* WihR = (const float*)d_in[4];  // (5,512,128)
    const float* Whh  = (const float*)d_in[5];  // (6,512,128)
    const float* bih  = (const float*)d_in[6];  // (6,512)
    const float* bhh  = (const float*)d_in[7];  // (6,512)
    float* out = (float*)d_out;                 // (6,64,128)

    const int GEMM_SMEM = 2 * 128 * 68 * 4;     // 69,632 B
    cudaFuncSetAttribute(gemm_xg<64>,  cudaFuncAttributeMaxDynamicSharedMemorySize, GEMM_SMEM);
    cudaFuncSetAttribute(gemm_xg<128>, cudaFuncAttributeMaxDynamicSharedMemorySize, GEMM_SMEM);

    dim3 ggrid(4, 1024);   // N-tiles x M-tiles

    // layer 0: input x (K=64), recur writes g_seq0 (osel=1)
    gemm_xg<64><<<ggrid, 256, GEMM_SMEM>>>(x, Wih0, 0);
    lstm_recur2<<<2 * BATCH, 256>>>(Whh, h0, c0, bih, bhh, 1, out);

    int insel = 1;
    for (int l = 1; l < NL; l++) {
        int outsel = (insel == 1) ? 2 : 1;
        gemm_xg<128><<<ggrid, 256, GEMM_SMEM>>>(
            nullptr, WihR + (size_t)(l - 1) * GDIM * HID, insel);
        lstm_recur2<<<2 * BATCH, 256>>>(
            Whh + (size_t)l * GDIM * HID,
            h0 + l * BATCH * HID,
            c0 + l * BATCH * HID,
            bih + l * GDIM,
            bhh + l * GDIM,
            outsel,
            out + l * BATCH * HID);
        insel = outsel;
    }
}

// round 10
// speedup vs baseline: 1.0980x; 1.0063x over previous
#include <cuda_runtime.h>
#include <cstddef>

// ---------------------------------------------------------------------------
// Problem constants (fixed by the dataset)
// ---------------------------------------------------------------------------
#define S_LEN 2048
#define BATCH 64
#define IN0   64
#define HID   128
#define GDIM  512          // 4*HID, PyTorch gate order: i, f, g, o
#define NL    6
#define MROWS (BATCH * S_LEN)   // 131072

// ---------------------------------------------------------------------------
// Static device scratch (no allocation allowed)
// ---------------------------------------------------------------------------
__device__ float g_xg  [(size_t)MROWS * GDIM];  // 256 MB: per-layer xg = seq @ Wih^T
__device__ float g_seq0[(size_t)MROWS * HID];   // 64 MB ping
__device__ float g_seq1[(size_t)MROWS * HID];   // 64 MB pong

typedef unsigned long long u64;

// ---------------------------------------------------------------------------
// f32x2 helpers (sm_103a packed fp32 pipe)
// ---------------------------------------------------------------------------
__device__ __forceinline__ u64 pk2(float a, float b) {
    u64 r;
    unsigned ua = __float_as_uint(a), ub = __float_as_uint(b);
    asm("mov.b64 %0, {%1, %2};" : "=l"(r) : "r"(ua), "r"(ub));
    return r;
}
__device__ __forceinline__ u64 ffma2(u64 a, u64 b, u64 c) {
    u64 d;
    asm("fma.rn.f32x2 %0, %1, %2, %3;" : "=l"(d) : "l"(a), "l"(b), "l"(c));
    return d;
}
__device__ __forceinline__ float2 upk2(u64 v) {
    unsigned lo, hi;
    asm("mov.b64 {%0, %1}, %2;" : "=r"(lo), "=r"(hi) : "l"(v));
    return make_float2(__uint_as_float(lo), __uint_as_float(hi));
}

__device__ __forceinline__ float sigf(float x)   { return 1.0f / (1.0f + __expf(-x)); }
__device__ __forceinline__ float tanh_f(float x) { return 2.0f * sigf(2.0f * x) - 1.0f; }

__device__ __forceinline__ unsigned sptr(const void* p) {
    return (unsigned)__cvta_generic_to_shared(p);
}

// ---------------------------------------------------------------------------
// GEMM: g_xg[r][n] = sum_k A[r][k] * W[n][k]   (unchanged)
// ---------------------------------------------------------------------------
template<int K>
__global__ __launch_bounds__(256, 1)
void gemm_xg(const float* __restrict__ Ax, const float* __restrict__ W, int asel)
{
    const float* A = (asel == 1) ? g_seq0 : (asel == 2) ? g_seq1 : Ax;
    extern __shared__ float sm[];
    float* As = sm;             // 128 x 68
    float* Bs = sm + 128 * 68;  // 128 x 68
    const int tx = threadIdx.x & 15;
    const int ty = threadIdx.x >> 4;
    const int row0 = blockIdx.y * 128;
    const int col0 = blockIdx.x * 128;

    u64 acc2[8][8];
#pragma unroll
    for (int i = 0; i < 8; i++)
#pragma unroll
        for (int j = 0; j < 8; j++) acc2[i][j] = 0ull;

    const int NCH = K / 64;
    for (int kc = 0; kc < NCH; kc++) {
        if (kc) __syncthreads();
#pragma unroll
        for (int p = 0; p < 8; p++) {
            int idx = threadIdx.x + 256 * p;
            int r = idx >> 4;
            int q = idx & 15;
            float4 av = *(const float4*)(A + (size_t)(row0 + r) * K + kc * 64 + 4 * q);
            *(float4*)(As + r * 68 + 4 * q) = av;
            float4 wv = *(const float4*)(W + (size_t)(col0 + r) * K + kc * 64 + 4 * q);
            *(float4*)(Bs + r * 68 + 4 * q) = wv;
        }
        __syncthreads();

        const ulonglong2* As2 = (const ulonglong2*)As;
        const ulonglong2* Bs2 = (const ulonglong2*)Bs;
        for (int kq = 0; kq < 16; kq++) {
            ulonglong2 b2[8];
#pragma unroll
            for (int j = 0; j < 8; j++) b2[j] = Bs2[(tx + 16 * j) * 17 + kq];
#pragma unroll
            for (int i = 0; i < 8; i++) {
                ulonglong2 a2 = As2[(ty + 16 * i) * 17 + kq];
#pragma unroll
                for (int j = 0; j < 8; j++) {
                    acc2[i][j] = ffma2(a2.x, b2[j].x, acc2[i][j]);
                    acc2[i][j] = ffma2(a2.y, b2[j].y, acc2[i][j]);
                }
            }
        }
    }

#pragma unroll
    for (int i = 0; i < 8; i++) {
        size_t rbase = (size_t)(row0 + ty + 16 * i) * GDIM + col0 + tx;
#pragma unroll
        for (int j = 0; j < 8; j++) {
            float2 p = upk2(acc2[i][j]);
            g_xg[rbase + 16 * j] = p.x + p.y;
        }
    }
}

// ---------------------------------------------------------------------------
// Recurrent kernel: cluster (2,1,1), minimal-sync protocol.
//   Identical to round 9 EXCEPT the per-step (and drain) try_wait uses
//   acquire.cta instead of acquire.cluster: cluster-scope acquire makes
//   ptxas emit CCTL.IVALL (full L1D invalidate) in every warp every step —
//   the round-5..9 hidden tax. The peer's st.shared::cluster +
//   arrive.release.cluster land in THIS CTA's SMEM over the same ordered
//   fabric path, so once the local barrier phase flips the data is local
//   and a CTA-scope acquire is sufficient (same pattern as the in-skill
//   MBARRIER_WAIT_PARITY reproducers).
// ---------------------------------------------------------------------------
__global__ __launch_bounds__(256, 1) __cluster_dims__(2, 1, 1)
void lstm_recur2(const float* __restrict__ Whh,   // (512,128) this layer
                 const float* __restrict__ h0,    // (64,128)
                 const float* __restrict__ c0,    // (64,128)
                 const float* __restrict__ bih,   // (512)
                 const float* __restrict__ bhh,   // (512)
                 int osel,                        // 1 -> g_seq0, 2 -> g_seq1
                 float* __restrict__ hT)          // (64,128) slice of output
{
    __shared__ alignas(16) float sH[2][HID];   // double-buffered hidden state
    __shared__ alignas(8) u64 mb_peer;         // 8 peer warp-arrives per step

    const int tid = threadIdx.x;
    const int l   = tid & 31;
    const int w   = tid >> 5;
    unsigned rank;
    asm("mov.u32 %0, %%cluster_ctarank;" : "=r"(rank));
    const int r = (int)rank;                   // 0 or 1
    const int b = blockIdx.x >> 1;             // batch row
    const int gt = l >> 3;                     // gate: 0=i 1=f 2=g 3=o
    const int hh = w * 8 + (l & 7);            // h sub-index 0..63
    const int grow = gt * HID + r * 64 + hh;   // global gate row
    const int hidx = r * 64 + hh;
    const bool upd = (l < 8);                  // i-lanes do the cell update
    float* seq_out = (osel == 1) ? g_seq0 : g_seq1;

    // ---- peer addresses ----
    const unsigned peer = rank ^ 1u;
    unsigned lsh0 = sptr(&sH[0][0]);
    unsigned lsh1 = sptr(&sH[1][0]);
    unsigned lmbp = sptr(&mb_peer);
    unsigned psh0, psh1, pmbp;
    asm("mapa.shared::cluster.u32 %0, %1, %2;" : "=r"(psh0) : "r"(lsh0), "r"(peer));
    asm("mapa.shared::cluster.u32 %0, %1, %2;" : "=r"(psh1) : "r"(lsh1), "r"(peer));
    asm("mapa.shared::cluster.u32 %0, %1, %2;" : "=r"(pmbp) : "r"(lmbp), "r"(peer));

    // ---- full Whh row into 64 u64 registers (pair q = k{2q,2q+1}) ----
    u64 w2[64];
    {
        const float* wrow = Whh + (size_t)grow * HID;
#pragma unroll
        for (int q = 0; q < 32; q++) {
            float4 v = *(const float4*)(wrow + 4 * q);
            w2[2 * q]     = pk2(v.x, v.y);
            w2[2 * q + 1] = pk2(v.z, v.w);
        }
    }
    const float biasg = bih[grow] + bhh[grow];
    const int lb = 32 * r;        // u64 base of local h half
    const int rb = 32 * (1 - r);  // u64 base of remote h half

    // ---- init ----
    if (tid < HID) sH[1][tid] = h0[b * HID + tid];
    float c = 0.0f, hlast = 0.0f;
    if (upd) c = c0[b * HID + hidx];
    if (tid == 0) {
        asm volatile("mbarrier.init.shared.b64 [%0], 8;" :: "r"(lmbp) : "memory");
    }
    __syncthreads();
    asm volatile("barrier.cluster.arrive.aligned;" ::: "memory");
    asm volatile("barrier.cluster.wait.aligned;"   ::: "memory");
    // prologue: one arrive per warp on the PEER's barrier -> completes phase 0
    if (l == 0) {
        asm volatile("mbarrier.arrive.release.cluster.shared::cluster.b64 _, [%0];"
                     :: "r"(pmbp) : "memory");
    }

    const float* xrow = g_xg + ((size_t)b * S_LEN) * GDIM + grow;
    float* orow = seq_out + ((size_t)b * S_LEN) * HID;

    float xcur = xrow[0];
    for (int t = 0; t < S_LEN; t++) {
        float xnext = (t + 1 < S_LEN) ? xrow[(size_t)(t + 1) * GDIM] : 0.0f;
        const u64* h2 = (const u64*)sH[(t + 1) & 1];
        const unsigned par = (unsigned)(t & 1);

        // ---- local-half matvec (local h visible via last step's bar.sync;
        //      runs while the peer's DSMEM store/arrive is in flight) ----
        u64 a0 = pk2(xcur + biasg, 0.0f);
        u64 a1 = 0ull, a2 = 0ull, a3 = 0ull;
#pragma unroll
        for (int q = 0; q < 8; q++) {
            a0 = ffma2(w2[lb + 4 * q + 0], h2[lb + 4 * q + 0], a0);
            a1 = ffma2(w2[lb + 4 * q + 1], h2[lb + 4 * q + 1], a1);
            a2 = ffma2(w2[lb + 4 * q + 2], h2[lb + 4 * q + 2], a2);
            a3 = ffma2(w2[lb + 4 * q + 3], h2[lb + 4 * q + 3], a3);
        }

        // ---- single wait: peer h half for this step (CTA-scope acquire:
        //      no CCTL.IVALL; see header comment) ----
        asm volatile(
            "{\n\t.reg .pred P;\n\t"
            "WB_%=:\n\t"
            "mbarrier.try_wait.parity.acquire.cta.shared::cta.b64 P, [%0], %1, 0x989680;\n\t"
            "@!P bra WB_%=;\n\t}"
            :: "r"(lmbp), "r"(par) : "memory");

        // ---- remote-half matvec ----
#pragma unroll
        for (int q = 0; q < 8; q++) {
            a0 = ffma2(w2[rb + 4 * q + 0], h2[rb + 4 * q + 0], a0);
            a1 = ffma2(w2[rb + 4 * q + 1], h2[rb + 4 * q + 1], a1);
            a2 = ffma2(w2[rb + 4 * q + 2], h2[rb + 4 * q + 2], a2);
            a3 = ffma2(w2[rb + 4 * q + 3], h2[rb + 4 * q + 3], a3);
        }
        float2 p0 = upk2(a0), p1 = upk2(a1), p2 = upk2(a2), p3 = upk2(a3);
        float raw = ((p0.x + p0.y) + (p1.x + p1.y)) + ((p2.x + p2.y) + (p3.x + p3.y));

        // ---- activation (uniform code, no divergence) ----
        float xx = (gt == 2) ? 2.0f * raw : raw;
        float s  = sigf(xx);
        float act = (gt == 2) ? (2.0f * s - 1.0f) : s;

        // ---- gather f,g,o into the i-lanes via shuffles (independent) ----
        const int base = l & 7;
        float fv = __shfl_sync(0xffffffffu, act, base + 8);
        float gv = __shfl_sync(0xffffffffu, act, base + 16);
        float ov = __shfl_sync(0xffffffffu, act, base + 24);

        // ---- cell/hidden update on lanes 0-7 of every warp ----
        const int wbuf = t & 1;
        if (upd) {
            float iv = act;
            c = fv * c + iv * gv;
            float h = ov * tanh_f(c);
            hlast = h;
            // remote store FIRST (peer needs it soonest)
            unsigned pdst = ((wbuf == 0) ? psh0 : psh1) + 4u * (unsigned)hidx;
            asm volatile("st.shared::cluster.f32 [%0], %1;" :: "r"(pdst), "f"(h) : "memory");
            sH[wbuf][hidx] = h;                               // local copy
            orow[(size_t)t * HID + hidx] = h;                 // sequence output
        }
        __syncwarp();
        // one arrive per warp; release covers the warp's DSMEM stores
        if (l == 0) {
            asm volatile("mbarrier.arrive.release.cluster.shared::cluster.b64 _, [%0];"
                         :: "r"(pmbp) : "memory");
        }
        __syncthreads();   // local h visibility for next step's local half
        xcur = xnext;
    }

    // ---- drain: consume step-2047 arrives (phase 2048, parity 0), then a
    //      final cluster barrier so no remote traffic outlives this CTA.
    asm volatile(
        "{\n\t.reg .pred P;\n\t"
        "WD_%=:\n\t"
        "mbarrier.try_wait.parity.acquire.cta.shared::cta.b64 P, [%0], 0, 0x989680;\n\t"
        "@!P bra WD_%=;\n\t}"
        :: "r"(lmbp) : "memory");
    asm volatile("barrier.cluster.arrive.aligned;" ::: "memory");
    asm volatile("barrier.cluster.wait.aligned;"   ::: "memory");

    if (upd) hT[b * HID + hidx] = hlast;
}

// ---------------------------------------------------------------------------
// Launch: per layer, GEMM (xg precompute) then recurrent scan.
// ---------------------------------------------------------------------------
extern "C" void kernel_launch(void* const* d_in, const int* in_sizes, int n_in,
                              void* d_out, int out_size)
{
    const float* x    = (const float*)d_in[0];  // (64,2048,64)
    const float* h0   = (const float*)d_in[1];  // (6,64,128)
    const float* c0   = (const float*)d_in[2];  // (6,64,128)
    const float* Wih0 = (const float*)d_in[3];  // (512,64)
    const float* WihR = (const float*)d_in[4];  // (5,512,128)
    const float* Whh  = (const float*)d_in[5];  // (6,512,128)
    const float* bih  = (const float*)d_in[6];  // (6,512)
    const float* bhh  = (const float*)d_in[7];  // (6,512)
    float* out = (float*)d_out;                 // (6,64,128)

    const int GEMM_SMEM = 2 * 128 * 68 * 4;     // 69,632 B
    cudaFuncSetAttribute(gemm_xg<64>,  cudaFuncAttributeMaxDynamicSharedMemorySize, GEMM_SMEM);
    cudaFuncSetAttribute(gemm_xg<128>, cudaFuncAttributeMaxDynamicSharedMemorySize, GEMM_SMEM);

    dim3 ggrid(4, 1024);   // N-tiles x M-tiles

    // layer 0: input x (K=64), recur writes g_seq0 (osel=1)
    gemm_xg<64><<<ggrid, 256, GEMM_SMEM>>>(x, Wih0, 0);
    lstm_recur2<<<2 * BATCH, 256>>>(Whh, h0, c0, bih, bhh, 1, out);

    int insel = 1;
    for (int l = 1; l < NL; l++) {
        int outsel = (insel == 1) ? 2 : 1;
        gemm_xg<128><<<ggrid, 256, GEMM_SMEM>>>(
            nullptr, WihR + (size_t)(l - 1) * GDIM * HID, insel);
        lstm_recur2<<<2 * BATCH, 256>>>(
            Whh + (size_t)l * GDIM * HID,
            h0 + l * BATCH * HID,
            c0 + l * BATCH * HID,
            bih + l * GDIM,
            bhh + l * GDIM,
            outsel,
            out + l * BATCH * HID);
        insel = outsel;
    }
}

// round 11
// speedup vs baseline: 1.1073x; 1.0085x over previous
#include <cuda_runtime.h>
#include <cstddef>

// ---------------------------------------------------------------------------
// Problem constants (fixed by the dataset)
// ---------------------------------------------------------------------------
#define S_LEN 2048
#define BATCH 64
#define IN0   64
#define HID   128
#define GDIM  512          // 4*HID, PyTorch gate order: i, f, g, o
#define NL    6
#define MROWS (BATCH * S_LEN)   // 131072

// ---------------------------------------------------------------------------
// Static device scratch (no allocation allowed)
// ---------------------------------------------------------------------------
__device__ float g_xg  [(size_t)MROWS * GDIM];  // 256 MB: per-layer xg = seq @ Wih^T
__device__ float g_seq0[(size_t)MROWS * HID];   // 64 MB ping
__device__ float g_seq1[(size_t)MROWS * HID];   // 64 MB pong

typedef unsigned long long u64;

// ---------------------------------------------------------------------------
// f32x2 helpers (sm_103a packed fp32 pipe)
// ---------------------------------------------------------------------------
__device__ __forceinline__ u64 pk2(float a, float b) {
    u64 r;
    unsigned ua = __float_as_uint(a), ub = __float_as_uint(b);
    asm("mov.b64 %0, {%1, %2};" : "=l"(r) : "r"(ua), "r"(ub));
    return r;
}
__device__ __forceinline__ u64 ffma2(u64 a, u64 b, u64 c) {
    u64 d;
    asm("fma.rn.f32x2 %0, %1, %2, %3;" : "=l"(d) : "l"(a), "l"(b), "l"(c));
    return d;
}
__device__ __forceinline__ float2 upk2(u64 v) {
    unsigned lo, hi;
    asm("mov.b64 {%0, %1}, %2;" : "=r"(lo), "=r"(hi) : "l"(v));
    return make_float2(__uint_as_float(lo), __uint_as_float(hi));
}

__device__ __forceinline__ float sigf(float x)   { return 1.0f / (1.0f + __expf(-x)); }
__device__ __forceinline__ float tanh_f(float x) { return 2.0f * sigf(2.0f * x) - 1.0f; }

__device__ __forceinline__ unsigned sptr(const void* p) {
    return (unsigned)__cvta_generic_to_shared(p);
}

// ---------------------------------------------------------------------------
// GEMM: g_xg[r][n] = sum_k A[r][k] * W[n][k]   (unchanged from round 6)
// ---------------------------------------------------------------------------
template<int K>
__global__ __launch_bounds__(256, 1)
void gemm_xg(const float* __restrict__ Ax, const float* __restrict__ W, int asel)
{
    const float* A = (asel == 1) ? g_seq0 : (asel == 2) ? g_seq1 : Ax;
    extern __shared__ float sm[];
    float* As = sm;             // 128 x 68
    float* Bs = sm + 128 * 68;  // 128 x 68
    const int tx = threadIdx.x & 15;
    const int ty = threadIdx.x >> 4;
    const int row0 = blockIdx.y * 128;
    const int col0 = blockIdx.x * 128;

    u64 acc2[8][8];
#pragma unroll
    for (int i = 0; i < 8; i++)
#pragma unroll
        for (int j = 0; j < 8; j++) acc2[i][j] = 0ull;

    const int NCH = K / 64;
    for (int kc = 0; kc < NCH; kc++) {
        if (kc) __syncthreads();
#pragma unroll
        for (int p = 0; p < 8; p++) {
            int idx = threadIdx.x + 256 * p;
            int r = idx >> 4;
            int q = idx & 15;
            float4 av = *(const float4*)(A + (size_t)(row0 + r) * K + kc * 64 + 4 * q);
            *(float4*)(As + r * 68 + 4 * q) = av;
            float4 wv = *(const float4*)(W + (size_t)(col0 + r) * K + kc * 64 + 4 * q);
            *(float4*)(Bs + r * 68 + 4 * q) = wv;
        }
        __syncthreads();

        const ulonglong2* As2 = (const ulonglong2*)As;
        const ulonglong2* Bs2 = (const ulonglong2*)Bs;
        for (int kq = 0; kq < 16; kq++) {
            ulonglong2 b2[8];
#pragma unroll
            for (int j = 0; j < 8; j++) b2[j] = Bs2[(tx + 16 * j) * 17 + kq];
#pragma unroll
            for (int i = 0; i < 8; i++) {
                ulonglong2 a2 = As2[(ty + 16 * i) * 17 + kq];
#pragma unroll
                for (int j = 0; j < 8; j++) {
                    acc2[i][j] = ffma2(a2.x, b2[j].x, acc2[i][j]);
                    acc2[i][j] = ffma2(a2.y, b2[j].y, acc2[i][j]);
                }
            }
        }
    }

#pragma unroll
    for (int i = 0; i < 8; i++) {
        size_t rbase = (size_t)(row0 + ty + 16 * i) * GDIM + col0 + tx;
#pragma unroll
        for (int j = 0; j < 8; j++) {
            float2 p = upk2(acc2[i][j]);
            g_xg[rbase + 16 * j] = p.x + p.y;
        }
    }
}

// ---------------------------------------------------------------------------
// Recurrent kernel = ROUND-6 STRUCTURE (best: 14.1ms) + split matvec.
//   2 CTAs per batch row (cluster (2,1,1)); rank r owns h[64r,64r+64).
//   256 threads, thread tid -> gate row grow = (tid>>6)*128 + r*64 + (tid&63).
//   Full Whh row in 64 u64 regs. Gates through sG SMEM; update on warps 0,1
//   (tid<64); two bar.syncs per step. ONE mbarrier (mb_peer, count 64,
//   remote release.cluster arrives only).
//   THE ONLY CHANGE vs round 6: the mbarrier wait sits BETWEEN the local and
//   remote halves of the dot product, so the peer's DSMEM store + fabric
//   flight (~300cyc) hides behind bar#2 + the local-half FMA chain.
//   Race freedom: my remote arrive is issued after bar#1, i.e. after ALL my
//   warps finished reading sH[(t+1)&1]; the peer's wait (phase t+1) therefore
//   certifies my reads before its next store targets that CTA-half.
//   Phase map: prologue completes phase 0; step t's arrives complete phase
//   t+1; step t waits parity t&1. Post-loop: drain phase 2048 (parity 0) +
//   cluster barrier so no remote traffic outlives a CTA.
// ---------------------------------------------------------------------------
__global__ __launch_bounds__(256, 1) __cluster_dims__(2, 1, 1)
void lstm_recur2(const float* __restrict__ Whh,   // (512,128) this layer
                 const float* __restrict__ h0,    // (64,128)
                 const float* __restrict__ c0,    // (64,128)
                 const float* __restrict__ bih,   // (512)
                 const float* __restrict__ bhh,   // (512)
                 int osel,                        // 1 -> g_seq0, 2 -> g_seq1
                 float* __restrict__ hT)          // (64,128) slice of output
{
    __shared__ alignas(16) float sH[2][HID];   // double-buffered hidden state
    __shared__ float sG[256];                  // activated gates (this CTA's rows)
    __shared__ alignas(8) u64 mb_peer;         // 64 peer updater arrives/step

    const int tid = threadIdx.x;
    unsigned rank;
    asm("mov.u32 %0, %%cluster_ctarank;" : "=r"(rank));
    const int r = (int)rank;                   // 0 or 1
    const int b = blockIdx.x >> 1;             // batch row
    const int gt = tid >> 6;                   // gate: 0=i 1=f 2=g 3=o (warp-uniform)
    const int j  = tid & 63;
    const int grow = gt * HID + r * 64 + j;    // global gate row
    const int hidx = r * 64 + j;
    float* seq_out = (osel == 1) ? g_seq0 : g_seq1;

    // ---- peer addresses ----
    const unsigned peer = rank ^ 1u;
    unsigned lsh0 = sptr(&sH[0][0]);
    unsigned lsh1 = sptr(&sH[1][0]);
    unsigned lmbp = sptr(&mb_peer);
    unsigned psh0, psh1, pmbp;
    asm("mapa.shared::cluster.u32 %0, %1, %2;" : "=r"(psh0) : "r"(lsh0), "r"(peer));
    asm("mapa.shared::cluster.u32 %0, %1, %2;" : "=r"(psh1) : "r"(lsh1), "r"(peer));
    asm("mapa.shared::cluster.u32 %0, %1, %2;" : "=r"(pmbp) : "r"(lmbp), "r"(peer));

    // ---- full Whh row into 64 u64 registers (pair q = k{2q,2q+1}) ----
    u64 w2[64];
    {
        const float* wrow = Whh + (size_t)grow * HID;
#pragma unroll
        for (int q = 0; q < 32; q++) {
            float4 v = *(const float4*)(wrow + 4 * q);
            w2[2 * q]     = pk2(v.x, v.y);
            w2[2 * q + 1] = pk2(v.z, v.w);
        }
    }
    const float biasg = bih[grow] + bhh[grow];
    const bool is_tanh = (gt == 2);
    const int lb = 32 * r;        // u64 base of local h half
    const int rb = 32 * (1 - r);  // u64 base of remote h half

    // ---- init: h0 into buffer 1 (read by step 0), c into updater regs ----
    if (tid < HID) sH[1][tid] = h0[b * HID + tid];
    float c = 0.0f, hlast = 0.0f;
    if (tid < 64) c = c0[b * HID + hidx];
    if (tid == 0) {
        asm volatile("mbarrier.init.shared.b64 [%0], 64;" :: "r"(lmbp) : "memory");
    }
    __syncthreads();
    asm volatile("barrier.cluster.arrive.aligned;" ::: "memory");
    asm volatile("barrier.cluster.wait.aligned;"   ::: "memory");
    // prologue: updaters arrive on the PEER's barrier -> completes phase 0
    if (tid < 64) {
        asm volatile("mbarrier.arrive.release.cluster.shared::cluster.b64 _, [%0];"
                     :: "r"(pmbp) : "memory");
    }

    const float* xrow = g_xg + ((size_t)b * S_LEN) * GDIM + grow;
    float* orow = seq_out + ((size_t)b * S_LEN) * HID;

    float xcur = xrow[0];
    for (int t = 0; t < S_LEN; t++) {
        float xnext = (t + 1 < S_LEN) ? xrow[(size_t)(t + 1) * GDIM] : 0.0f;
        const u64* h2 = (const u64*)sH[(t + 1) & 1];
        const unsigned par = (unsigned)(t & 1);

        // ---- local-half matvec (local h visible via last step's bar#2;
        //      runs while the peer's DSMEM store + arrive are in flight) ----
        u64 a0 = pk2(xcur + biasg, 0.0f);
        u64 a1 = 0ull, a2 = 0ull, a3 = 0ull;
#pragma unroll
        for (int q = 0; q < 8; q++) {
            a0 = ffma2(w2[lb + 4 * q + 0], h2[lb + 4 * q + 0], a0);
            a1 = ffma2(w2[lb + 4 * q + 1], h2[lb + 4 * q + 1], a1);
            a2 = ffma2(w2[lb + 4 * q + 2], h2[lb + 4 * q + 2], a2);
            a3 = ffma2(w2[lb + 4 * q + 3], h2[lb + 4 * q + 3], a3);
        }

        // ---- wait peer h half for this step (CTA-scope acquire: the
        //      sender's release.cluster + point-to-point fabric order the
        //      store before the flip; validated correct in round 10) ----
        asm volatile(
            "{\n\t.reg .pred P;\n\t"
            "WB_%=:\n\t"
            "mbarrier.try_wait.parity.acquire.cta.shared::cta.b64 P, [%0], %1, 0x989680;\n\t"
            "@!P bra WB_%=;\n\t}"
            :: "r"(lmbp), "r"(par) : "memory");

        // ---- remote-half matvec ----
#pragma unroll
        for (int q = 0; q < 8; q++) {
            a0 = ffma2(w2[rb + 4 * q + 0], h2[rb + 4 * q + 0], a0);
            a1 = ffma2(w2[rb + 4 * q + 1], h2[rb + 4 * q + 1], a1);
            a2 = ffma2(w2[rb + 4 * q + 2], h2[rb + 4 * q + 2], a2);
            a3 = ffma2(w2[rb + 4 * q + 3], h2[rb + 4 * q + 3], a3);
        }
        float2 p0 = upk2(a0), p1 = upk2(a1), p2 = upk2(a2), p3 = upk2(a3);
        float raw = ((p0.x + p0.y) + (p1.x + p1.y)) + ((p2.x + p2.y) + (p3.x + p3.y));
        sG[tid] = is_tanh ? tanh_f(raw) : sigf(raw);
        __syncthreads();   // bar#1: gates visible; ALL warps done reading sH

        // ---- cell/hidden update on warps 0,1 (tid<64) ----
        if (tid < 64) {
            float iv = sG[tid], fv = sG[tid + 64], gv = sG[tid + 128], ov = sG[tid + 192];
            c = fv * c + iv * gv;
            float h = ov * tanh_f(c);
            hlast = h;
            const int wbuf = t & 1;
            // remote store first (peer needs it soonest), then its arrive
            unsigned pdst = ((wbuf == 0) ? psh0 : psh1) + 4u * (unsigned)hidx;
            asm volatile("st.shared::cluster.f32 [%0], %1;" :: "r"(pdst), "f"(h) : "memory");
            asm volatile("mbarrier.arrive.release.cluster.shared::cluster.b64 _, [%0];"
                         :: "r"(pmbp) : "memory");
            sH[wbuf][hidx] = h;                               // local copy
            orow[(size_t)t * HID + hidx] = h;                 // sequence output
        }
        __syncthreads();   // bar#2: local sH visible for next local half
        xcur = xnext;
    }

    // ---- drain: consume step-2047 arrives (phase 2048, parity 0), then a
    //      final cluster barrier so no remote traffic outlives this CTA.
    asm volatile(
        "{\n\t.reg .pred P;\n\t"
        "WD_%=:\n\t"
        "mbarrier.try_wait.parity.acquire.cta.shared::cta.b64 P, [%0], 0, 0x989680;\n\t"
        "@!P bra WD_%=;\n\t}"
        :: "r"(lmbp) : "memory");
    asm volatile("barrier.cluster.arrive.aligned;" ::: "memory");
    asm volatile("barrier.cluster.wait.aligned;"   ::: "memory");

    if (tid < 64) hT[b * HID + hidx] = hlast;
}

// ---------------------------------------------------------------------------
// Launch: per layer, GEMM (xg precompute) then recurrent scan.
// ---------------------------------------------------------------------------
extern "C" void kernel_launch(void* const* d_in, const int* in_sizes, int n_in,
                              void* d_out, int out_size)
{
    const float* x    = (const float*)d_in[0];  // (64,2048,64)
    const float* h0   = (const float*)d_in[1];  // (6,64,128)
    const float* c0   = (const float*)d_in[2];  // (6,64,128)
    const float* Wih0 = (const float*)d_in[3];  // (512,64)
    const float* WihR = (const float*)d_in[4];  // (5,512,128)
    const float* Whh  = (const float*)d_in[5];  // (6,512,128)
    const float* bih  = (const float*)d_in[6];  // (6,512)
    const float* bhh  = (const float*)d_in[7];  // (6,512)
    float* out = (float*)d_out;                 // (6,64,128)

    const int GEMM_SMEM = 2 * 128 * 68 * 4;     // 69,632 B
    cudaFuncSetAttribute(gemm_xg<64>,  cudaFuncAttributeMaxDynamicSharedMemorySize, GEMM_SMEM);
    cudaFuncSetAttribute(gemm_xg<128>, cudaFuncAttributeMaxDynamicSharedMemorySize, GEMM_SMEM);

    dim3 ggrid(4, 1024);   // N-tiles x M-tiles

    // layer 0: input x (K=64), recur writes g_seq0 (osel=1)
    gemm_xg<64><<<ggrid, 256, GEMM_SMEM>>>(x, Wih0, 0);
    lstm_recur2<<<2 * BATCH, 256>>>(Whh, h0, c0, bih, bhh, 1, out);

    int insel = 1;
    for (int l = 1; l < NL; l++) {
        int outsel = (insel == 1) ? 2 : 1;
        gemm_xg<128><<<ggrid, 256, GEMM_SMEM>>>(
            nullptr, WihR + (size_t)(l - 1) * GDIM * HID, insel);
        lstm_recur2<<<2 * BATCH, 256>>>(
            Whh + (size_t)l * GDIM * HID,
            h0 + l * BATCH * HID,
            c0 + l * BATCH * HID,
            bih + l * GDIM,
            bhh + l * GDIM,
            outsel,
            out + l * BATCH * HID);
        insel = outsel;
    }
}

// round 12
// speedup vs baseline: 1.1181x; 1.0098x over previous
#include <cuda_runtime.h>
#include <cstddef>

// ---------------------------------------------------------------------------
// Problem constants (fixed by the dataset)
// ---------------------------------------------------------------------------
#define S_LEN 2048
#define BATCH 64
#define IN0   64
#define HID   128
#define GDIM  512          // 4*HID, PyTorch gate order: i, f, g, o
#define NL    6
#define MROWS (BATCH * S_LEN)   // 131072

// ---------------------------------------------------------------------------
// Static device scratch (no allocation allowed)
// ---------------------------------------------------------------------------
__device__ float g_xg  [(size_t)MROWS * GDIM];  // 256 MB: per-layer xg = seq @ Wih^T
__device__ float g_seq0[(size_t)MROWS * HID];   // 64 MB ping
__device__ float g_seq1[(size_t)MROWS * HID];   // 64 MB pong

typedef unsigned long long u64;

// ---------------------------------------------------------------------------
// f32x2 helpers (sm_103a packed fp32 pipe)
// ---------------------------------------------------------------------------
__device__ __forceinline__ u64 pk2(float a, float b) {
    u64 r;
    unsigned ua = __float_as_uint(a), ub = __float_as_uint(b);
    asm("mov.b64 %0, {%1, %2};" : "=l"(r) : "r"(ua), "r"(ub));
    return r;
}
__device__ __forceinline__ u64 ffma2(u64 a, u64 b, u64 c) {
    u64 d;
    asm("fma.rn.f32x2 %0, %1, %2, %3;" : "=l"(d) : "l"(a), "l"(b), "l"(c));
    return d;
}
__device__ __forceinline__ float2 upk2(u64 v) {
    unsigned lo, hi;
    asm("mov.b64 {%0, %1}, %2;" : "=r"(lo), "=r"(hi) : "l"(v));
    return make_float2(__uint_as_float(lo), __uint_as_float(hi));
}

__device__ __forceinline__ float sigf(float x)   { return 1.0f / (1.0f + __expf(-x)); }
__device__ __forceinline__ float tanh_f(float x) { return 2.0f * sigf(2.0f * x) - 1.0f; }

__device__ __forceinline__ unsigned sptr(const void* p) {
    return (unsigned)__cvta_generic_to_shared(p);
}

// ---------------------------------------------------------------------------
// GEMM: g_xg[r][n] = sum_k A[r][k] * W[n][k]   (unchanged from round 6)
// ---------------------------------------------------------------------------
template<int K>
__global__ __launch_bounds__(256, 1)
void gemm_xg(const float* __restrict__ Ax, const float* __restrict__ W, int asel)
{
    const float* A = (asel == 1) ? g_seq0 : (asel == 2) ? g_seq1 : Ax;
    extern __shared__ float sm[];
    float* As = sm;             // 128 x 68
    float* Bs = sm + 128 * 68;  // 128 x 68
    const int tx = threadIdx.x & 15;
    const int ty = threadIdx.x >> 4;
    const int row0 = blockIdx.y * 128;
    const int col0 = blockIdx.x * 128;

    u64 acc2[8][8];
#pragma unroll
    for (int i = 0; i < 8; i++)
#pragma unroll
        for (int j = 0; j < 8; j++) acc2[i][j] = 0ull;

    const int NCH = K / 64;
    for (int kc = 0; kc < NCH; kc++) {
        if (kc) __syncthreads();
#pragma unroll
        for (int p = 0; p < 8; p++) {
            int idx = threadIdx.x + 256 * p;
            int r = idx >> 4;
            int q = idx & 15;
            float4 av = *(const float4*)(A + (size_t)(row0 + r) * K + kc * 64 + 4 * q);
            *(float4*)(As + r * 68 + 4 * q) = av;
            float4 wv = *(const float4*)(W + (size_t)(col0 + r) * K + kc * 64 + 4 * q);
            *(float4*)(Bs + r * 68 + 4 * q) = wv;
        }
        __syncthreads();

        const ulonglong2* As2 = (const ulonglong2*)As;
        const ulonglong2* Bs2 = (const ulonglong2*)Bs;
        for (int kq = 0; kq < 16; kq++) {
            ulonglong2 b2[8];
#pragma unroll
            for (int j = 0; j < 8; j++) b2[j] = Bs2[(tx + 16 * j) * 17 + kq];
#pragma unroll
            for (int i = 0; i < 8; i++) {
                ulonglong2 a2 = As2[(ty + 16 * i) * 17 + kq];
#pragma unroll
                for (int j = 0; j < 8; j++) {
                    acc2[i][j] = ffma2(a2.x, b2[j].x, acc2[i][j]);
                    acc2[i][j] = ffma2(a2.y, b2[j].y, acc2[i][j]);
                }
            }
        }
    }

#pragma unroll
    for (int i = 0; i < 8; i++) {
        size_t rbase = (size_t)(row0 + ty + 16 * i) * GDIM + col0 + tx;
#pragma unroll
        for (int j = 0; j < 8; j++) {
            float2 p = upk2(acc2[i][j]);
            g_xg[rbase + 16 * j] = p.x + p.y;
        }
    }
}

// ---------------------------------------------------------------------------
// Recurrent kernel = round-11 structure with ONE fix: h reads are LDS.128
// (ulonglong2), 16 per half, matching the fast rounds 5/6. Rounds 8-11 all
// used LDS.64 h reads (64/thread) — +32 issue slots/thread and +256 crossbar
// wavefronts/step, ~+400 cyc/step — the real source of the 14.1 -> 19-21ms
// regression, previously misattributed to the sync protocol.
//   Cluster (2,1,1), rank r owns h[64r,64r+64). 256 threads, one gate row
//   per thread, full Whh row in 64 u64 regs. Split matvec (local half ->
//   wait peer -> remote half) hides the DSMEM exchange. Gates via sG SMEM,
//   update on warps 0,1; one count-64 peer mbarrier; acquire.cta wait
//   (HW-validated in round 10). Drain + final cluster barrier per round 7.
// ---------------------------------------------------------------------------
__global__ __launch_bounds__(256, 1) __cluster_dims__(2, 1, 1)
void lstm_recur2(const float* __restrict__ Whh,   // (512,128) this layer
                 const float* __restrict__ h0,    // (64,128)
                 const float* __restrict__ c0,    // (64,128)
                 const float* __restrict__ bih,   // (512)
                 const float* __restrict__ bhh,   // (512)
                 int osel,                        // 1 -> g_seq0, 2 -> g_seq1
                 float* __restrict__ hT)          // (64,128) slice of output
{
    __shared__ alignas(16) float sH[2][HID];   // double-buffered hidden state
    __shared__ float sG[256];                  // activated gates (this CTA's rows)
    __shared__ alignas(8) u64 mb_peer;         // 64 peer updater arrives/step

    const int tid = threadIdx.x;
    unsigned rank;
    asm("mov.u32 %0, %%cluster_ctarank;" : "=r"(rank));
    const int r = (int)rank;                   // 0 or 1
    const int b = blockIdx.x >> 1;             // batch row
    const int gt = tid >> 6;                   // gate: 0=i 1=f 2=g 3=o (warp-uniform)
    const int j  = tid & 63;
    const int grow = gt * HID + r * 64 + j;    // global gate row
    const int hidx = r * 64 + j;
    float* seq_out = (osel == 1) ? g_seq0 : g_seq1;

    // ---- peer addresses ----
    const unsigned peer = rank ^ 1u;
    unsigned lsh0 = sptr(&sH[0][0]);
    unsigned lsh1 = sptr(&sH[1][0]);
    unsigned lmbp = sptr(&mb_peer);
    unsigned psh0, psh1, pmbp;
    asm("mapa.shared::cluster.u32 %0, %1, %2;" : "=r"(psh0) : "r"(lsh0), "r"(peer));
    asm("mapa.shared::cluster.u32 %0, %1, %2;" : "=r"(psh1) : "r"(lsh1), "r"(peer));
    asm("mapa.shared::cluster.u32 %0, %1, %2;" : "=r"(pmbp) : "r"(lmbp), "r"(peer));

    // ---- full Whh row into 64 u64 registers (pair q = k{2q,2q+1}) ----
    u64 w2[64];
    {
        const float* wrow = Whh + (size_t)grow * HID;
#pragma unroll
        for (int q = 0; q < 32; q++) {
            float4 v = *(const float4*)(wrow + 4 * q);
            w2[2 * q]     = pk2(v.x, v.y);
            w2[2 * q + 1] = pk2(v.z, v.w);
        }
    }
    const float biasg = bih[grow] + bhh[grow];
    const bool is_tanh = (gt == 2);
    const int lb  = 32 * r;        // u64 base of local h half (weights)
    const int rb  = 32 * (1 - r);  // u64 base of remote h half (weights)
    const int lb2 = 16 * r;        // ulonglong2 base of local h half
    const int rb2 = 16 * (1 - r);  // ulonglong2 base of remote h half

    // ---- init: h0 into buffer 1 (read by step 0), c into updater regs ----
    if (tid < HID) sH[1][tid] = h0[b * HID + tid];
    float c = 0.0f, hlast = 0.0f;
    if (tid < 64) c = c0[b * HID + hidx];
    if (tid == 0) {
        asm volatile("mbarrier.init.shared.b64 [%0], 64;" :: "r"(lmbp) : "memory");
    }
    __syncthreads();
    asm volatile("barrier.cluster.arrive.aligned;" ::: "memory");
    asm volatile("barrier.cluster.wait.aligned;"   ::: "memory");
    // prologue: updaters arrive on the PEER's barrier -> completes phase 0
    if (tid < 64) {
        asm volatile("mbarrier.arrive.release.cluster.shared::cluster.b64 _, [%0];"
                     :: "r"(pmbp) : "memory");
    }

    const float* xrow = g_xg + ((size_t)b * S_LEN) * GDIM + grow;
    float* orow = seq_out + ((size_t)b * S_LEN) * HID;

    float xcur = xrow[0];
    for (int t = 0; t < S_LEN; t++) {
        float xnext = (t + 1 < S_LEN) ? xrow[(size_t)(t + 1) * GDIM] : 0.0f;
        const ulonglong2* h4 = (const ulonglong2*)sH[(t + 1) & 1];
        const unsigned par = (unsigned)(t & 1);

        // ---- local-half matvec: 16 LDS.128 + 32 ffma2 (runs while the
        //      peer's DSMEM store + arrive are in flight) ----
        u64 a0 = pk2(xcur + biasg, 0.0f);
        u64 a1 = 0ull, a2 = 0ull, a3 = 0ull;
#pragma unroll
        for (int q = 0; q < 8; q++) {
            ulonglong2 hA = h4[lb2 + 2 * q];
            ulonglong2 hB = h4[lb2 + 2 * q + 1];
            a0 = ffma2(w2[lb + 4 * q + 0], hA.x, a0);
            a1 = ffma2(w2[lb + 4 * q + 1], hA.y, a1);
            a2 = ffma2(w2[lb + 4 * q + 2], hB.x, a2);
            a3 = ffma2(w2[lb + 4 * q + 3], hB.y, a3);
        }

        // ---- wait peer h half for this step (CTA-scope acquire) ----
        asm volatile(
            "{\n\t.reg .pred P;\n\t"
            "WB_%=:\n\t"
            "mbarrier.try_wait.parity.acquire.cta.shared::cta.b64 P, [%0], %1, 0x989680;\n\t"
            "@!P bra WB_%=;\n\t}"
            :: "r"(lmbp), "r"(par) : "memory");

        // ---- remote-half matvec: 16 LDS.128 + 32 ffma2 ----
#pragma unroll
        for (int q = 0; q < 8; q++) {
            ulonglong2 hA = h4[rb2 + 2 * q];
            ulonglong2 hB = h4[rb2 + 2 * q + 1];
            a0 = ffma2(w2[rb + 4 * q + 0], hA.x, a0);
            a1 = ffma2(w2[rb + 4 * q + 1], hA.y, a1);
            a2 = ffma2(w2[rb + 4 * q + 2], hB.x, a2);
            a3 = ffma2(w2[rb + 4 * q + 3], hB.y, a3);
        }
        float2 p0 = upk2(a0), p1 = upk2(a1), p2 = upk2(a2), p3 = upk2(a3);
        float raw = ((p0.x + p0.y) + (p1.x + p1.y)) + ((p2.x + p2.y) + (p3.x + p3.y));
        sG[tid] = is_tanh ? tanh_f(raw) : sigf(raw);
        __syncthreads();   // bar#1: gates visible; ALL warps done reading sH

        // ---- cell/hidden update on warps 0,1 (tid<64) ----
        if (tid < 64) {
            float iv = sG[tid], fv = sG[tid + 64], gv = sG[tid + 128], ov = sG[tid + 192];
            c = fv * c + iv * gv;
            float h = ov * tanh_f(c);
            hlast = h;
            const int wbuf = t & 1;
            // remote store first (peer needs it soonest), then its arrive
            unsigned pdst = ((wbuf == 0) ? psh0 : psh1) + 4u * (unsigned)hidx;
            asm volatile("st.shared::cluster.f32 [%0], %1;" :: "r"(pdst), "f"(h) : "memory");
            asm volatile("mbarrier.arrive.release.cluster.shared::cluster.b64 _, [%0];"
                         :: "r"(pmbp) : "memory");
            sH[wbuf][hidx] = h;                               // local copy
            orow[(size_t)t * HID + hidx] = h;                 // sequence output
        }
        __syncthreads();   // bar#2: local sH visible for next local half
        xcur = xnext;
    }

    // ---- drain: consume step-2047 arrives (phase 2048, parity 0), then a
    //      final cluster barrier so no remote traffic outlives this CTA.
    asm volatile(
        "{\n\t.reg .pred P;\n\t"
        "WD_%=:\n\t"
        "mbarrier.try_wait.parity.acquire.cta.shared::cta.b64 P, [%0], 0, 0x989680;\n\t"
        "@!P bra WD_%=;\n\t}"
        :: "r"(lmbp) : "memory");
    asm volatile("barrier.cluster.arrive.aligned;" ::: "memory");
    asm volatile("barrier.cluster.wait.aligned;"   ::: "memory");

    if (tid < 64) hT[b * HID + hidx] = hlast;
}

// ---------------------------------------------------------------------------
// Launch: per layer, GEMM (xg precompute) then recurrent scan.
// ---------------------------------------------------------------------------
extern "C" void kernel_launch(void* const* d_in, const int* in_sizes, int n_in,
                              void* d_out, int out_size)
{
    const float* x    = (const float*)d_in[0];  // (64,2048,64)
    const float* h0   = (const float*)d_in[1];  // (6,64,128)
    const float* c0   = (const float*)d_in[2];  // (6,64,128)
    const float* Wih0 = (const float*)d_in[3];  // (512,64)
    const float* WihR = (const float*)d_in[4];  // (5,512,128)
    const float* Whh  = (const float*)d_in[5];  // (6,512,128)
    const float* bih  = (const float*)d_in[6];  // (6,512)
    const float* bhh  = (const float*)d_in[7];  // (6,512)
    float* out = (float*)d_out;                 // (6,64,128)

    const int GEMM_SMEM = 2 * 128 * 68 * 4;     // 69,632 B
    cudaFuncSetAttribute(gemm_xg<64>,  cudaFuncAttributeMaxDynamicSharedMemorySize, GEMM_SMEM);
    cudaFuncSetAttribute(gemm_xg<128>, cudaFuncAttributeMaxDynamicSharedMemorySize, GEMM_SMEM);

    dim3 ggrid(4, 1024);   // N-tiles x M-tiles

    // layer 0: input x (K=64), recur writes g_seq0 (osel=1)
    gemm_xg<64><<<ggrid, 256, GEMM_SMEM>>>(x, Wih0, 0);
    lstm_recur2<<<2 * BATCH, 256>>>(Whh, h0, c0, bih, bhh, 1, out);

    int insel = 1;
    for (int l = 1; l < NL; l++) {
        int outsel = (insel == 1) ? 2 : 1;
        gemm_xg<128><<<ggrid, 256, GEMM_SMEM>>>(
            nullptr, WihR + (size_t)(l - 1) * GDIM * HID, insel);
        lstm_recur2<<<2 * BATCH, 256>>>(
            Whh + (size_t)l * GDIM * HID,
            h0 + l * BATCH * HID,
            c0 + l * BATCH * HID,
            bih + l * GDIM,
            bhh + l * GDIM,
            outsel,
            out + l * BATCH * HID);
        insel = outsel;
    }
}

// round 14
// speedup vs baseline: 1.1491x; 1.0277x over previous
#include <cuda_runtime.h>
#include <cstddef>

// ---------------------------------------------------------------------------
// Problem constants (fixed by the dataset)
// ---------------------------------------------------------------------------
#define S_LEN 2048
#define BATCH 64
#define IN0   64
#define HID   128
#define GDIM  512          // 4*HID, PyTorch gate order: i, f, g, o
#define NL    6
#define MROWS (BATCH * S_LEN)   // 131072

// ---------------------------------------------------------------------------
// Static device scratch (no allocation allowed)
// ---------------------------------------------------------------------------
__device__ float g_xg  [(size_t)MROWS * GDIM];  // 256 MB: per-layer xg = seq @ Wih^T
__device__ float g_seq0[(size_t)MROWS * HID];   // 64 MB ping
__device__ float g_seq1[(size_t)MROWS * HID];   // 64 MB pong

typedef unsigned long long u64;

// ---------------------------------------------------------------------------
// f32x2 helpers (sm_103a packed fp32 pipe)
// ---------------------------------------------------------------------------
__device__ __forceinline__ u64 pk2(float a, float b) {
    u64 r;
    unsigned ua = __float_as_uint(a), ub = __float_as_uint(b);
    asm("mov.b64 %0, {%1, %2};" : "=l"(r) : "r"(ua), "r"(ub));
    return r;
}
__device__ __forceinline__ u64 ffma2(u64 a, u64 b, u64 c) {
    u64 d;
    asm("fma.rn.f32x2 %0, %1, %2, %3;" : "=l"(d) : "l"(a), "l"(b), "l"(c));
    return d;
}
__device__ __forceinline__ float2 upk2(u64 v) {
    unsigned lo, hi;
    asm("mov.b64 {%0, %1}, %2;" : "=r"(lo), "=r"(hi) : "l"(v));
    return make_float2(__uint_as_float(lo), __uint_as_float(hi));
}

__device__ __forceinline__ float sigf(float x)   { return 1.0f / (1.0f + __expf(-x)); }
__device__ __forceinline__ float tanh_f(float x) { return 2.0f * sigf(2.0f * x) - 1.0f; }

__device__ __forceinline__ unsigned sptr(const void* p) {
    return (unsigned)__cvta_generic_to_shared(p);
}

// ---------------------------------------------------------------------------
// GEMM: g_xg[r][n] = sum_k A[r][k] * W[n][k]   (unchanged from round 6)
// ---------------------------------------------------------------------------
template<int K>
__global__ __launch_bounds__(256, 1)
void gemm_xg(const float* __restrict__ Ax, const float* __restrict__ W, int asel)
{
    const float* A = (asel == 1) ? g_seq0 : (asel == 2) ? g_seq1 : Ax;
    extern __shared__ float sm[];
    float* As = sm;             // 128 x 68
    float* Bs = sm + 128 * 68;  // 128 x 68
    const int tx = threadIdx.x & 15;
    const int ty = threadIdx.x >> 4;
    const int row0 = blockIdx.y * 128;
    const int col0 = blockIdx.x * 128;

    u64 acc2[8][8];
#pragma unroll
    for (int i = 0; i < 8; i++)
#pragma unroll
        for (int j = 0; j < 8; j++) acc2[i][j] = 0ull;

    const int NCH = K / 64;
    for (int kc = 0; kc < NCH; kc++) {
        if (kc) __syncthreads();
#pragma unroll
        for (int p = 0; p < 8; p++) {
            int idx = threadIdx.x + 256 * p;
            int r = idx >> 4;
            int q = idx & 15;
            float4 av = *(const float4*)(A + (size_t)(row0 + r) * K + kc * 64 + 4 * q);
            *(float4*)(As + r * 68 + 4 * q) = av;
            float4 wv = *(const float4*)(W + (size_t)(col0 + r) * K + kc * 64 + 4 * q);
            *(float4*)(Bs + r * 68 + 4 * q) = wv;
        }
        __syncthreads();

        const ulonglong2* As2 = (const ulonglong2*)As;
        const ulonglong2* Bs2 = (const ulonglong2*)Bs;
        for (int kq = 0; kq < 16; kq++) {
            ulonglong2 b2[8];
#pragma unroll
            for (int j = 0; j < 8; j++) b2[j] = Bs2[(tx + 16 * j) * 17 + kq];
#pragma unroll
            for (int i = 0; i < 8; i++) {
                ulonglong2 a2 = As2[(ty + 16 * i) * 17 + kq];
#pragma unroll
                for (int j = 0; j < 8; j++) {
                    acc2[i][j] = ffma2(a2.x, b2[j].x, acc2[i][j]);
                    acc2[i][j] = ffma2(a2.y, b2[j].y, acc2[i][j]);
                }
            }
        }
    }

#pragma unroll
    for (int i = 0; i < 8; i++) {
        size_t rbase = (size_t)(row0 + ty + 16 * i) * GDIM + col0 + tx;
#pragma unroll
        for (int j = 0; j < 8; j++) {
            float2 p = upk2(acc2[i][j]);
            g_xg[rbase + 16 * j] = p.x + p.y;
        }
    }
}

// ---------------------------------------------------------------------------
// Recurrent kernel: TWO batch rows per cluster, R6-EXACT phase protocol.
//   Phase map (the round-13 deadlock fix): NO prologue arrives. Step t's
//   arrives complete phase t; the end-of-step wait on parity t&1 (phase t)
//   genuinely BLOCKS until both CTAs finish step t. (Round 13 added prologue
//   arrives, shifting arrives to phase t+1 while waits targeted phase t ->
//   waits never blocked -> CTAs drifted -> mbarrier arrival-count overflow
//   -> corrupted barrier -> hang.)
//   32 clusters x 2 CTAs x 256 threads; rank r owns h[64r,64r+64) of both
//   rows. Thread -> gate row (tid>>6)*128 + r*64 + (tid&63), same 128 weight
//   registers serve both rows' dot products; row B's independent FMA/LDS
//   stream fills row A's sync-latency slots. Updates: tid<64 row0,
//   tid 64..127 row1. Per-row count-128 mbarrier (64 local release.cta +
//   64 peer release.cluster arrives per step). Update order exactly R6:
//   local sH write -> local arrive -> DSMEM store -> peer arrive.
//   Exit: final wait (t=2047) consumes phase 2047 incl. the peer's last
//   release-arrives (stores precede them) -> same exit proof as R6; plus a
//   final cluster barrier.
// ---------------------------------------------------------------------------
__global__ __launch_bounds__(256, 1) __cluster_dims__(2, 1, 1)
void lstm_recur2(const float* __restrict__ Whh,   // (512,128) this layer
                 const float* __restrict__ h0,    // (64,128)
                 const float* __restrict__ c0,    // (64,128)
                 const float* __restrict__ bih,   // (512)
                 const float* __restrict__ bhh,   // (512)
                 int osel,                        // 1 -> g_seq0, 2 -> g_seq1
                 float* __restrict__ hT)          // (64,128) slice of output
{
    __shared__ alignas(16) float sH[2][2][HID];  // [row][buf][h]
    __shared__ float sG[2][256];                 // activated gates per row
    __shared__ alignas(8) u64 mb[2];             // per-row barrier, count 128

    const int tid = threadIdx.x;
    unsigned rank;
    asm("mov.u32 %0, %%cluster_ctarank;" : "=r"(rank));
    const int r = (int)rank;                   // 0 or 1
    const int bp = blockIdx.x >> 1;            // batch pair index 0..31
    const int b0 = 2 * bp, b1 = 2 * bp + 1;
    const int gt = tid >> 6;                   // gate: 0=i 1=f 2=g 3=o
    const int j  = tid & 63;
    const int grow = gt * HID + r * 64 + j;    // global gate row (both rows)
    float* seq_out = (osel == 1) ? g_seq0 : g_seq1;

    // ---- peer addresses ----
    const unsigned peer = rank ^ 1u;
    unsigned lsh  = sptr(&sH[0][0][0]);
    unsigned lmb0 = sptr(&mb[0]);
    unsigned lmb1 = sptr(&mb[1]);
    unsigned psh, pmb0, pmb1;
    asm("mapa.shared::cluster.u32 %0, %1, %2;" : "=r"(psh)  : "r"(lsh),  "r"(peer));
    asm("mapa.shared::cluster.u32 %0, %1, %2;" : "=r"(pmb0) : "r"(lmb0), "r"(peer));
    asm("mapa.shared::cluster.u32 %0, %1, %2;" : "=r"(pmb1) : "r"(lmb1), "r"(peer));

    // ---- full Whh row into 64 u64 registers (pair q = k{2q,2q+1}) ----
    u64 w2[64];
    {
        const float* wrow = Whh + (size_t)grow * HID;
#pragma unroll
        for (int q = 0; q < 32; q++) {
            float4 v = *(const float4*)(wrow + 4 * q);
            w2[2 * q]     = pk2(v.x, v.y);
            w2[2 * q + 1] = pk2(v.z, v.w);
        }
    }
    const float biasg = bih[grow] + bhh[grow];
    const bool is_tanh = (gt == 2);

    // ---- update-role mapping: tid<64 -> row0, tid in [64,128) -> row1 ----
    const int urow = tid >> 6;                 // valid for tid<128
    const int uid  = tid & 63;
    const int hidx = r * 64 + uid;
    const bool upd = (tid < 128);
    unsigned lmb_r = urow ? lmb1 : lmb0;
    unsigned pmb_r = urow ? pmb1 : pmb0;

    // ---- init ----
    if (tid < HID) sH[0][1][tid] = h0[b0 * HID + tid];
    else           sH[1][1][tid - HID] = h0[b1 * HID + (tid - HID)];
    float c = 0.0f, hlast = 0.0f;
    if (upd) c = c0[(urow ? b1 : b0) * HID + hidx];
    if (tid == 0) {
        asm volatile("mbarrier.init.shared.b64 [%0], 128;" :: "r"(lmb0) : "memory");
        asm volatile("mbarrier.init.shared.b64 [%0], 128;" :: "r"(lmb1) : "memory");
    }
    __syncthreads();
    asm volatile("barrier.cluster.arrive.aligned;" ::: "memory");
    asm volatile("barrier.cluster.wait.aligned;"   ::: "memory");
    // NO prologue arrives: step t's arrives complete phase t (R6 protocol).

    const float* xrow0 = g_xg + ((size_t)b0 * S_LEN) * GDIM + grow;
    const float* xrow1 = g_xg + ((size_t)b1 * S_LEN) * GDIM + grow;
    float* orow0 = seq_out + ((size_t)b0 * S_LEN) * HID;
    float* orow1 = seq_out + ((size_t)b1 * S_LEN) * HID;

    float xc0 = xrow0[0];
    float xc1 = xrow1[0];
    for (int t = 0; t < S_LEN; t++) {
        float xn0 = (t + 1 < S_LEN) ? xrow0[(size_t)(t + 1) * GDIM] : 0.0f;
        float xn1 = (t + 1 < S_LEN) ? xrow1[(size_t)(t + 1) * GDIM] : 0.0f;
        const int rbuf = (t + 1) & 1;
        const ulonglong2* h40 = (const ulonglong2*)sH[0][rbuf];
        const ulonglong2* h41 = (const ulonglong2*)sH[1][rbuf];
        const unsigned par = (unsigned)(t & 1);

        // ---- dual matvec: both rows share w2; independent streams ----
        u64 a0 = pk2(xc0 + biasg, 0.0f);
        u64 a1 = 0ull, a2 = 0ull, a3 = 0ull;
        u64 d0 = pk2(xc1 + biasg, 0.0f);
        u64 d1 = 0ull, d2 = 0ull, d3 = 0ull;
#pragma unroll
        for (int q = 0; q < 16; q++) {
            ulonglong2 hA0 = h40[2 * q];
            ulonglong2 hB0 = h40[2 * q + 1];
            ulonglong2 hA1 = h41[2 * q];
            ulonglong2 hB1 = h41[2 * q + 1];
            a0 = ffma2(w2[4 * q + 0], hA0.x, a0);
            d0 = ffma2(w2[4 * q + 0], hA1.x, d0);
            a1 = ffma2(w2[4 * q + 1], hA0.y, a1);
            d1 = ffma2(w2[4 * q + 1], hA1.y, d1);
            a2 = ffma2(w2[4 * q + 2], hB0.x, a2);
            d2 = ffma2(w2[4 * q + 2], hB1.x, d2);
            a3 = ffma2(w2[4 * q + 3], hB0.y, a3);
            d3 = ffma2(w2[4 * q + 3], hB1.y, d3);
        }
        {
            float2 p0 = upk2(a0), p1 = upk2(a1), p2 = upk2(a2), p3 = upk2(a3);
            float raw0 = ((p0.x + p0.y) + (p1.x + p1.y)) + ((p2.x + p2.y) + (p3.x + p3.y));
            float2 q0 = upk2(d0), q1 = upk2(d1), q2 = upk2(d2), q3 = upk2(d3);
            float raw1 = ((q0.x + q0.y) + (q1.x + q1.y)) + ((q2.x + q2.y) + (q3.x + q3.y));
            if (is_tanh) {
                sG[0][tid] = tanh_f(raw0);
                sG[1][tid] = tanh_f(raw1);
            } else {
                sG[0][tid] = sigf(raw0);
                sG[1][tid] = sigf(raw1);
            }
        }
        __syncthreads();   // bar#1: gates visible; ALL warps done reading sH

        // ---- cell/hidden update: tid<64 row0, tid 64..127 row1 ----
        const int wbuf = t & 1;
        if (upd) {
            const float* sGr = sG[urow];
            float iv = sGr[uid], fv = sGr[uid + 64], gv = sGr[uid + 128], ov = sGr[uid + 192];
            c = fv * c + iv * gv;
            float h = ov * tanh_f(c);
            hlast = h;
            sH[urow][wbuf][hidx] = h;                         // local copy
            asm volatile("mbarrier.arrive.release.cta.shared::cta.b64 _, [%0];"
                         :: "r"(lmb_r) : "memory");
            unsigned pdst = psh + 4u * (unsigned)(urow * 2 * HID + wbuf * HID + hidx);
            asm volatile("st.shared::cluster.f32 [%0], %1;" :: "r"(pdst), "f"(h) : "memory");
            asm volatile("mbarrier.arrive.release.cluster.shared::cluster.b64 _, [%0];"
                         :: "r"(pmb_r) : "memory");
            (urow ? orow1 : orow0)[(size_t)t * HID + hidx] = h;
        }

        // ---- end-of-step waits: phase t on both row barriers (BLOCKING:
        //      requires this step's 64 local + 64 peer arrives per row) ----
        asm volatile(
            "{\n\t.reg .pred P;\n\t"
            "W0_%=:\n\t"
            "mbarrier.try_wait.parity.acquire.cta.shared::cta.b64 P, [%0], %1, 0x989680;\n\t"
            "@!P bra W0_%=;\n\t}"
            :: "r"(lmb0), "r"(par) : "memory");
        asm volatile(
            "{\n\t.reg .pred P;\n\t"
            "W1_%=:\n\t"
            "mbarrier.try_wait.parity.acquire.cta.shared::cta.b64 P, [%0], %1, 0x989680;\n\t"
            "@!P bra W1_%=;\n\t}"
            :: "r"(lmb1), "r"(par) : "memory");

        xc0 = xn0;
        xc1 = xn1;
    }

    // ---- exit: final in-loop wait already consumed the peer's last arrives
    //      (its stores precede them); cluster barrier as final guard.
    asm volatile("barrier.cluster.arrive.aligned;" ::: "memory");
    asm volatile("barrier.cluster.wait.aligned;"   ::: "memory");

    if (upd) hT[(urow ? b1 : b0) * HID + hidx] = hlast;
}

// ---------------------------------------------------------------------------
// Launch: per layer, GEMM (xg precompute) then recurrent scan.
// ---------------------------------------------------------------------------
extern "C" void kernel_launch(void* const* d_in, const int* in_sizes, int n_in,
                              void* d_out, int out_size)
{
    const float* x    = (const float*)d_in[0];  // (64,2048,64)
    const float* h0   = (const float*)d_in[1];  // (6,64,128)
    const float* c0   = (const float*)d_in[2];  // (6,64,128)
    const float* Wih0 = (const float*)d_in[3];  // (512,64)
    const float* WihR = (const float*)d_in[4];  // (5,512,128)
    const float* Whh  = (const float*)d_in[5];  // (6,512,128)
    const float* bih  = (const float*)d_in[6];  // (6,512)
    const float* bhh  = (const float*)d_in[7];  // (6,512)
    float* out = (float*)d_out;                 // (6,64,128)

    const int GEMM_SMEM = 2 * 128 * 68 * 4;     // 69,632 B
    cudaFuncSetAttribute(gemm_xg<64>,  cudaFuncAttributeMaxDynamicSharedMemorySize, GEMM_SMEM);
    cudaFuncSetAttribute(gemm_xg<128>, cudaFuncAttributeMaxDynamicSharedMemorySize, GEMM_SMEM);

    dim3 ggrid(4, 1024);   // N-tiles x M-tiles

    // layer 0: input x (K=64), recur writes g_seq0 (osel=1)
    gemm_xg<64><<<ggrid, 256, GEMM_SMEM>>>(x, Wih0, 0);
    lstm_recur2<<<BATCH, 256>>>(Whh, h0, c0, bih, bhh, 1, out);  // 64 CTAs = 32 clusters

    int insel = 1;
    for (int l = 1; l < NL; l++) {
        int outsel = (insel == 1) ? 2 : 1;
        gemm_xg<128><<<ggrid, 256, GEMM_SMEM>>>(
            nullptr, WihR + (size_t)(l - 1) * GDIM * HID, insel);
        lstm_recur2<<<BATCH, 256>>>(
            Whh + (size_t)l * GDIM * HID,
            h0 + l * BATCH * HID,
            c0 + l * BATCH * HID,
            bih + l * GDIM,
            bhh + l * GDIM,
            outsel,
            out + l * BATCH * HID);
        insel = outsel;
    }
}

// round 15
// speedup vs baseline: 1.4608x; 1.2712x over previous
#include <cuda_runtime.h>
#include <cstddef>

// ---------------------------------------------------------------------------
// Problem constants (fixed by the dataset)
// ---------------------------------------------------------------------------
#define S_LEN 2048
#define BATCH 64
#define IN0   64
#define HID   128
#define GDIM  512          // 4*HID, PyTorch gate order: i, f, g, o
#define NL    6
#define MROWS (BATCH * S_LEN)   // 131072

// ---------------------------------------------------------------------------
// Static device scratch (no allocation allowed)
// ---------------------------------------------------------------------------
__device__ float g_xg  [(size_t)MROWS * GDIM];  // 256 MB: per-layer xg = seq @ Wih^T
__device__ float g_seq0[(size_t)MROWS * HID];   // 64 MB ping
__device__ float g_seq1[(size_t)MROWS * HID];   // 64 MB pong

typedef unsigned long long u64;

// ---------------------------------------------------------------------------
// f32x2 helpers (sm_103a packed fp32 pipe)
// ---------------------------------------------------------------------------
__device__ __forceinline__ u64 pk2(float a, float b) {
    u64 r;
    unsigned ua = __float_as_uint(a), ub = __float_as_uint(b);
    asm("mov.b64 %0, {%1, %2};" : "=l"(r) : "r"(ua), "r"(ub));
    return r;
}
__device__ __forceinline__ u64 ffma2(u64 a, u64 b, u64 c) {
    u64 d;
    asm("fma.rn.f32x2 %0, %1, %2, %3;" : "=l"(d) : "l"(a), "l"(b), "l"(c));
    return d;
}
__device__ __forceinline__ float2 upk2(u64 v) {
    unsigned lo, hi;
    asm("mov.b64 {%0, %1}, %2;" : "=r"(lo), "=r"(hi) : "l"(v));
    return make_float2(__uint_as_float(lo), __uint_as_float(hi));
}

__device__ __forceinline__ float sigf(float x)   { return 1.0f / (1.0f + __expf(-x)); }
__device__ __forceinline__ float tanh_f(float x) { return 2.0f * sigf(2.0f * x) - 1.0f; }

__device__ __forceinline__ unsigned sptr(const void* p) {
    return (unsigned)__cvta_generic_to_shared(p);
}

// ---------------------------------------------------------------------------
// GEMM: g_xg[r][n] = sum_k A[r][k] * W[n][k]   (unchanged from round 6)
// ---------------------------------------------------------------------------
template<int K>
__global__ __launch_bounds__(256, 1)
void gemm_xg(const float* __restrict__ Ax, const float* __restrict__ W, int asel)
{
    const float* A = (asel == 1) ? g_seq0 : (asel == 2) ? g_seq1 : Ax;
    extern __shared__ float sm[];
    float* As = sm;             // 128 x 68
    float* Bs = sm + 128 * 68;  // 128 x 68
    const int tx = threadIdx.x & 15;
    const int ty = threadIdx.x >> 4;
    const int row0 = blockIdx.y * 128;
    const int col0 = blockIdx.x * 128;

    u64 acc2[8][8];
#pragma unroll
    for (int i = 0; i < 8; i++)
#pragma unroll
        for (int j = 0; j < 8; j++) acc2[i][j] = 0ull;

    const int NCH = K / 64;
    for (int kc = 0; kc < NCH; kc++) {
        if (kc) __syncthreads();
#pragma unroll
        for (int p = 0; p < 8; p++) {
            int idx = threadIdx.x + 256 * p;
            int r = idx >> 4;
            int q = idx & 15;
            float4 av = *(const float4*)(A + (size_t)(row0 + r) * K + kc * 64 + 4 * q);
            *(float4*)(As + r * 68 + 4 * q) = av;
            float4 wv = *(const float4*)(W + (size_t)(col0 + r) * K + kc * 64 + 4 * q);
            *(float4*)(Bs + r * 68 + 4 * q) = wv;
        }
        __syncthreads();

        const ulonglong2* As2 = (const ulonglong2*)As;
        const ulonglong2* Bs2 = (const ulonglong2*)Bs;
        for (int kq = 0; kq < 16; kq++) {
            ulonglong2 b2[8];
#pragma unroll
            for (int j = 0; j < 8; j++) b2[j] = Bs2[(tx + 16 * j) * 17 + kq];
#pragma unroll
            for (int i = 0; i < 8; i++) {
                ulonglong2 a2 = As2[(ty + 16 * i) * 17 + kq];
#pragma unroll
                for (int j = 0; j < 8; j++) {
                    acc2[i][j] = ffma2(a2.x, b2[j].x, acc2[i][j]);
                    acc2[i][j] = ffma2(a2.y, b2[j].y, acc2[i][j]);
                }
            }
        }
    }

#pragma unroll
    for (int i = 0; i < 8; i++) {
        size_t rbase = (size_t)(row0 + ty + 16 * i) * GDIM + col0 + tx;
#pragma unroll
        for (int j = 0; j < 8; j++) {
            float2 p = upk2(acc2[i][j]);
            g_xg[rbase + 16 * j] = p.x + p.y;
        }
    }
}

// ---------------------------------------------------------------------------
// Recurrent kernel = EXACT round-6 protocol (the 14,086us best: one batch row
// per 2-CTA cluster, full unsplit matvec with LDS.128 h reads, gates via sG,
// update on warps 0-1, ONE count-128 mbarrier, single wait at STEP END on
// parity t&1, no prologue arrives) + ONE change:
//   WARP-AGGREGATED ARRIVES. R6 issued 128 same-address mbarrier arrives per
//   step per barrier word (64 local release.cta + 64 peer release.cluster).
//   Same-address SMEM atomics serialize (~32cyc/warp class) and each remote
//   arrive occupies the fabric — the suspected ~800cyc/step hidden cost.
//   Now: each updater warp finishes its stores, __syncwarp, then LANE 0
//   issues ONE arrive with count=32 locally and count=32 on the peer.
//   Arrivals per barrier word per step: 128 -> 4. The release after
//   __syncwarp preserves the visibility chain (warp's stores happen-before
//   lane 0's release-arrive).
// ---------------------------------------------------------------------------
__global__ __launch_bounds__(256, 1) __cluster_dims__(2, 1, 1)
void lstm_recur2(const float* __restrict__ Whh,   // (512,128) this layer
                 const float* __restrict__ h0,    // (64,128)
                 const float* __restrict__ c0,    // (64,128)
                 const float* __restrict__ bih,   // (512)
                 const float* __restrict__ bhh,   // (512)
                 int osel,                        // 1 -> g_seq0, 2 -> g_seq1
                 float* __restrict__ hT)          // (64,128) slice of output
{
    __shared__ alignas(16) float sH[2][HID];   // double-buffered hidden state
    __shared__ float sG[256];                  // activated gates (this CTA's rows)
    __shared__ alignas(8) u64 mbar;            // count 128 (2x count-32 local +
                                               //            2x count-32 peer)

    const int tid = threadIdx.x;
    unsigned rank;
    asm("mov.u32 %0, %%cluster_ctarank;" : "=r"(rank));
    const int r = (int)rank;                   // 0 or 1
    const int b = blockIdx.x >> 1;             // batch row
    const int gt = tid >> 6;                   // gate: 0=i 1=f 2=g 3=o
    const int j  = tid & 63;
    const int grow = gt * HID + r * 64 + j;    // global gate row
    const int hidx = r * 64 + j;
    float* seq_out = (osel == 1) ? g_seq0 : g_seq1;

    // ---- remote (peer CTA) shared-memory addresses ----
    const unsigned peer = rank ^ 1u;
    unsigned lsh0 = sptr(&sH[0][0]);
    unsigned lsh1 = sptr(&sH[1][0]);
    unsigned lmb  = sptr(&mbar);
    unsigned psh0, psh1, pmb;
    asm("mapa.shared::cluster.u32 %0, %1, %2;" : "=r"(psh0) : "r"(lsh0), "r"(peer));
    asm("mapa.shared::cluster.u32 %0, %1, %2;" : "=r"(psh1) : "r"(lsh1), "r"(peer));
    asm("mapa.shared::cluster.u32 %0, %1, %2;" : "=r"(pmb)  : "r"(lmb),  "r"(peer));

    // ---- load this thread's full Whh row into 64 u64 registers ----
    u64 w2[64];
    {
        const float* wrow = Whh + (size_t)grow * HID;
#pragma unroll
        for (int q = 0; q < 32; q++) {
            float4 v = *(const float4*)(wrow + 4 * q);
            w2[2 * q]     = pk2(v.x, v.y);
            w2[2 * q + 1] = pk2(v.z, v.w);
        }
    }
    const float biasg = bih[grow] + bhh[grow];
    const bool is_tanh = (gt == 2);

    // ---- init: h0 into buffer 1 (read by step 0), c into updater regs ----
    if (tid < HID) sH[1][tid] = h0[b * HID + tid];
    float c = 0.0f, hlast = 0.0f;
    if (tid < 64) c = c0[b * HID + hidx];
    if (tid == 0) {
        asm volatile("mbarrier.init.shared.b64 [%0], 128;" :: "r"(lmb) : "memory");
    }
    __syncthreads();
    // all mbarrier inits + sH fills visible cluster-wide before any arrives
    asm volatile("barrier.cluster.arrive.aligned;" ::: "memory");
    asm volatile("barrier.cluster.wait.aligned;"   ::: "memory");
    // NO prologue arrives: step t's arrives complete phase t (R6 phase map).

    const float* xrow = g_xg + ((size_t)b * S_LEN) * GDIM + grow;
    float* orow = seq_out + ((size_t)b * S_LEN) * HID;

    float xcur = xrow[0];
    for (int t = 0; t < S_LEN; t++) {
        float xnext = (t + 1 < S_LEN) ? xrow[(size_t)(t + 1) * GDIM] : 0.0f;

        // ---- matvec: gate[grow] = xg + bias + dot(Whh[grow], h_prev) ----
        const ulonglong2* h4 = (const ulonglong2*)sH[(t + 1) & 1];
        u64 a0 = pk2(xcur + biasg, 0.0f);
        u64 a1 = 0ull, a2 = 0ull, a3 = 0ull;
#pragma unroll
        for (int q = 0; q < 16; q++) {
            ulonglong2 hA = h4[2 * q];
            ulonglong2 hB = h4[2 * q + 1];
            a0 = ffma2(w2[4 * q + 0], hA.x, a0);
            a1 = ffma2(w2[4 * q + 1], hA.y, a1);
            a2 = ffma2(w2[4 * q + 2], hB.x, a2);
            a3 = ffma2(w2[4 * q + 3], hB.y, a3);
        }
        float2 p0 = upk2(a0), p1 = upk2(a1), p2 = upk2(a2), p3 = upk2(a3);
        float raw = ((p0.x + p0.y) + (p1.x + p1.y)) + ((p2.x + p2.y) + (p3.x + p3.y));
        sG[tid] = is_tanh ? tanh_f(raw) : sigf(raw);
        __syncthreads();   // all 256 gates of this CTA visible to updaters
                           // (also certifies: ALL warps done reading sH)

        // ---- cell/hidden update for this CTA's 64 h-indices (warps 0,1) ----
        const int wbuf = t & 1;
        if (tid < 64) {
            float iv = sG[tid], fv = sG[tid + 64], gv = sG[tid + 128], ov = sG[tid + 192];
            c = fv * c + iv * gv;
            float h = ov * tanh_f(c);
            hlast = h;
            sH[wbuf][hidx] = h;                               // local copy
            unsigned pdst = ((wbuf == 0) ? psh0 : psh1) + 4u * (unsigned)hidx;
            asm volatile("st.shared::cluster.f32 [%0], %1;" :: "r"(pdst), "f"(h) : "memory");
            orow[(size_t)t * HID + hidx] = h;                 // sequence output
            // warp-aggregated arrives: whole warp's stores done -> lane 0
            // releases with count 32 (local) + count 32 (peer).
            __syncwarp(0xffffffffu);
            if ((tid & 31) == 0) {
                asm volatile("mbarrier.arrive.release.cta.shared::cta.b64 _, [%0], 32;"
                             :: "r"(lmb) : "memory");
                asm volatile("mbarrier.arrive.release.cluster.shared::cluster.b64 _, [%0], 32;"
                             :: "r"(pmb) : "memory");
            }
        }

        // ---- single wait at STEP END: phase t (parity t&1), blocking on
        //      64 local + 64 peer arrival-counts for this step ----
        {
            unsigned par = (unsigned)(t & 1);
            asm volatile(
                "{\n\t.reg .pred P;\n\t"
                "WL_%=:\n\t"
                "mbarrier.try_wait.parity.acquire.cta.shared::cta.b64 P, [%0], %1, 0x989680;\n\t"
                "@!P bra WL_%=;\n\t}"
                :: "r"(lmb), "r"(par) : "memory");
        }
        xcur = xnext;
    }

    // exit: final in-loop wait consumed the peer's last arrives (its DSMEM
    // stores precede them). Cluster barrier as a one-time exit guard.
    asm volatile("barrier.cluster.arrive.aligned;" ::: "memory");
    asm volatile("barrier.cluster.wait.aligned;"   ::: "memory");

    if (tid < 64) hT[b * HID + hidx] = hlast;
}

// ---------------------------------------------------------------------------
// Launch: per layer, GEMM (xg precompute) then recurrent scan.
// ---------------------------------------------------------------------------
extern "C" void kernel_launch(void* const* d_in, const int* in_sizes, int n_in,
                              void* d_out, int out_size)
{
    const float* x    = (const float*)d_in[0];  // (64,2048,64)
    const float* h0   = (const float*)d_in[1];  // (6,64,128)
    const float* c0   = (const float*)d_in[2];  // (6,64,128)
    const float* Wih0 = (const float*)d_in[3];  // (512,64)
    const float* WihR = (const float*)d_in[4];  // (5,512,128)
    const float* Whh  = (const float*)d_in[5];  // (6,512,128)
    const float* bih  = (const float*)d_in[6];  // (6,512)
    const float* bhh  = (const float*)d_in[7];  // (6,512)
    float* out = (float*)d_out;                 // (6,64,128)

    const int GEMM_SMEM = 2 * 128 * 68 * 4;     // 69,632 B
    cudaFuncSetAttribute(gemm_xg<64>,  cudaFuncAttributeMaxDynamicSharedMemorySize, GEMM_SMEM);
    cudaFuncSetAttribute(gemm_xg<128>, cudaFuncAttributeMaxDynamicSharedMemorySize, GEMM_SMEM);

    dim3 ggrid(4, 1024);   // N-tiles x M-tiles

    // layer 0: input x (K=64), recur writes g_seq0 (osel=1)
    gemm_xg<64><<<ggrid, 256, GEMM_SMEM>>>(x, Wih0, 0);
    lstm_recur2<<<2 * BATCH, 256>>>(Whh, h0, c0, bih, bhh, 1, out);

    int insel = 1;
    for (int l = 1; l < NL; l++) {
        int outsel = (insel == 1) ? 2 : 1;
        gemm_xg<128><<<ggrid, 256, GEMM_SMEM>>>(
            nullptr, WihR + (size_t)(l - 1) * GDIM * HID, insel);
        lstm_recur2<<<2 * BATCH, 256>>>(
            Whh + (size_t)l * GDIM * HID,
            h0 + l * BATCH * HID,
            c0 + l * BATCH * HID,
            bih + l * GDIM,
            bhh + l * GDIM,
            outsel,
            out + l * BATCH * HID);
        insel = outsel;
    }
}

// round 16
// speedup vs baseline: 1.5330x; 1.0495x over previous
#include <cuda_runtime.h>
#include <cstddef>

// ---------------------------------------------------------------------------
// Problem constants (fixed by the dataset)
// ---------------------------------------------------------------------------
#define S_LEN 2048
#define BATCH 64
#define IN0   64
#define HID   128
#define GDIM  512          // 4*HID, PyTorch gate order: i, f, g, o
#define NL    6
#define MROWS (BATCH * S_LEN)   // 131072

// ---------------------------------------------------------------------------
// Static device scratch (no allocation allowed)
// ---------------------------------------------------------------------------
__device__ float g_xg  [(size_t)MROWS * GDIM];  // 256 MB: per-layer xg = seq @ Wih^T
__device__ float g_seq0[(size_t)MROWS * HID];   // 64 MB ping
__device__ float g_seq1[(size_t)MROWS * HID];   // 64 MB pong

typedef unsigned long long u64;

// ---------------------------------------------------------------------------
// f32x2 helpers (sm_103a packed fp32 pipe)
// ---------------------------------------------------------------------------
__device__ __forceinline__ u64 pk2(float a, float b) {
    u64 r;
    unsigned ua = __float_as_uint(a), ub = __float_as_uint(b);
    asm("mov.b64 %0, {%1, %2};" : "=l"(r) : "r"(ua), "r"(ub));
    return r;
}
__device__ __forceinline__ u64 ffma2(u64 a, u64 b, u64 c) {
    u64 d;
    asm("fma.rn.f32x2 %0, %1, %2, %3;" : "=l"(d) : "l"(a), "l"(b), "l"(c));
    return d;
}
__device__ __forceinline__ float2 upk2(u64 v) {
    unsigned lo, hi;
    asm("mov.b64 {%0, %1}, %2;" : "=r"(lo), "=r"(hi) : "l"(v));
    return make_float2(__uint_as_float(lo), __uint_as_float(hi));
}

__device__ __forceinline__ float sigf(float x)   { return 1.0f / (1.0f + __expf(-x)); }
__device__ __forceinline__ float tanh_f(float x) { return 2.0f * sigf(2.0f * x) - 1.0f; }

// ---------------------------------------------------------------------------
// GEMM: g_xg[r][n] = sum_k A[r][k] * W[n][k]   (unchanged from round 6)
// ---------------------------------------------------------------------------
template<int K>
__global__ __launch_bounds__(256, 1)
void gemm_xg(const float* __restrict__ Ax, const float* __restrict__ W, int asel)
{
    const float* A = (asel == 1) ? g_seq0 : (asel == 2) ? g_seq1 : Ax;
    extern __shared__ float sm[];
    float* As = sm;             // 128 x 68
    float* Bs = sm + 128 * 68;  // 128 x 68
    const int tx = threadIdx.x & 15;
    const int ty = threadIdx.x >> 4;
    const int row0 = blockIdx.y * 128;
    const int col0 = blockIdx.x * 128;

    u64 acc2[8][8];
#pragma unroll
    for (int i = 0; i < 8; i++)
#pragma unroll
        for (int j = 0; j < 8; j++) acc2[i][j] = 0ull;

    const int NCH = K / 64;
    for (int kc = 0; kc < NCH; kc++) {
        if (kc) __syncthreads();
#pragma unroll
        for (int p = 0; p < 8; p++) {
            int idx = threadIdx.x + 256 * p;
            int r = idx >> 4;
            int q = idx & 15;
            float4 av = *(const float4*)(A + (size_t)(row0 + r) * K + kc * 64 + 4 * q);
            *(float4*)(As + r * 68 + 4 * q) = av;
            float4 wv = *(const float4*)(W + (size_t)(col0 + r) * K + kc * 64 + 4 * q);
            *(float4*)(Bs + r * 68 + 4 * q) = wv;
        }
        __syncthreads();

        const ulonglong2* As2 = (const ulonglong2*)As;
        const ulonglong2* Bs2 = (const ulonglong2*)Bs;
        for (int kq = 0; kq < 16; kq++) {
            ulonglong2 b2[8];
#pragma unroll
            for (int j = 0; j < 8; j++) b2[j] = Bs2[(tx + 16 * j) * 17 + kq];
#pragma unroll
            for (int i = 0; i < 8; i++) {
                ulonglong2 a2 = As2[(ty + 16 * i) * 17 + kq];
#pragma unroll
                for (int j = 0; j < 8; j++) {
                    acc2[i][j] = ffma2(a2.x, b2[j].x, acc2[i][j]);
                    acc2[i][j] = ffma2(a2.y, b2[j].y, acc2[i][j]);
                }
            }
        }
    }

#pragma unroll
    for (int i = 0; i < 8; i++) {
        size_t rbase = (size_t)(row0 + ty + 16 * i) * GDIM + col0 + tx;
#pragma unroll
        for (int j = 0; j < 8; j++) {
            float2 p = upk2(acc2[i][j]);
            g_xg[rbase + 16 * j] = p.x + p.y;
        }
    }
}

// ---------------------------------------------------------------------------
// Recurrent kernel: SINGLE CTA PER BATCH ROW (no cluster, no mbarrier, no
// DSMEM — the cross-SM exchange chain proved to be the irreducible ~800cyc
// cost of the cluster design).
//   256 threads; thread tid owns TWO gate rows:
//     row A = tid        (gates i/f; sigmoid — warp-uniform)
//     row B = tid + 256  (gates g/o; tanh for warps 0-3, sigmoid 4-7)
//   Weight residency (capacity-engineered to fit ONE SM):
//     row A: all 128 cols in regs (64 u64)
//     row B: cols 0-31 in regs (16 u64); cols 32-127 in SMEM
//            (256 rows x 100-float padded stride -> conflict-free LDS.128:
//             lane l offset 100l floats -> bank group 4l mod 32, distinct
//             per 8-lane phase)
//   Per step: 128 ffma2, 32 broadcast LDS.128 (h; read once, used for both
//   rows), 24 strided LDS.128 (B-smem), 2x LDG xg prefetch, act, bar#1,
//   update (h-idx = tid for tid<128), bar#2.
//   Crossbar/step ~= 768 (B) + 256 (h) wf ~= 1050cyc; tail ~350 -> ~1400cyc
//   vs ~2000 for the cluster version.
// ---------------------------------------------------------------------------
#define WB_STRIDE 100    // floats per SMEM B-row (96 data + 4 pad)
#define RECUR_SMEM ((256 * WB_STRIDE + 2 * HID + GDIM + 8) * 4)

__global__ __launch_bounds__(256, 1)
void lstm_recur1(const float* __restrict__ Whh,   // (512,128) this layer
                 const float* __restrict__ h0,    // (64,128)
                 const float* __restrict__ c0,    // (64,128)
                 const float* __restrict__ bih,   // (512)
                 const float* __restrict__ bhh,   // (512)
                 int osel,                        // 1 -> g_seq0, 2 -> g_seq1
                 float* __restrict__ hT)          // (64,128) slice of output
{
    extern __shared__ float smem[];
    float* sWB = smem;                          // 256 x 100 (B cols 32..127)
    float* sHb = smem + 256 * WB_STRIDE;        // 2 x 128 (double-buffered h)
    float* sG  = sHb + 2 * HID;                 // 512 activated gates

    const int tid = threadIdx.x;
    const int b = blockIdx.x;                   // batch row
    const int rowA = tid;                       // i/f gates
    const int rowB = tid + 256;                 // g/o gates
    float* seq_out = (osel == 1) ? g_seq0 : g_seq1;

    // ---- row A weights: 128 cols into 64 u64 regs ----
    u64 wA[64];
    {
        const float* wr = Whh + (size_t)rowA * HID;
#pragma unroll
        for (int q = 0; q < 32; q++) {
            float4 v = *(const float4*)(wr + 4 * q);
            wA[2 * q]     = pk2(v.x, v.y);
            wA[2 * q + 1] = pk2(v.z, v.w);
        }
    }
    // ---- row B weights: cols 0..31 into 16 u64 regs, cols 32..127 to SMEM --
    u64 wB[16];
    {
        const float* wr = Whh + (size_t)rowB * HID;
#pragma unroll
        for (int q = 0; q < 8; q++) {
            float4 v = *(const float4*)(wr + 4 * q);
            wB[2 * q]     = pk2(v.x, v.y);
            wB[2 * q + 1] = pk2(v.z, v.w);
        }
        float* dst = sWB + tid * WB_STRIDE;
#pragma unroll
        for (int q = 0; q < 24; q++)
            *(float4*)(dst + 4 * q) = *(const float4*)(wr + 32 + 4 * q);
    }
    const float biasA = bih[rowA] + bhh[rowA];
    const float biasB = bih[rowB] + bhh[rowB];
    const bool tanhB = (tid < 128);             // rowB in [256,384) = g gate

    // ---- init: h0 into buffer 1 (read by step 0), c in updater regs ----
    if (tid < HID) sHb[HID + tid] = h0[b * HID + tid];
    float c = 0.0f, hlast = 0.0f;
    if (tid < HID) c = c0[b * HID + tid];
    __syncthreads();

    const float* xrA = g_xg + ((size_t)b * S_LEN) * GDIM + rowA;
    const float* xrB = g_xg + ((size_t)b * S_LEN) * GDIM + rowB;
    float* orow = seq_out + ((size_t)b * S_LEN) * HID;
    const ulonglong2* pB = (const ulonglong2*)(sWB + tid * WB_STRIDE);

    float xcA = xrA[0];
    float xcB = xrB[0];
    for (int t = 0; t < S_LEN; t++) {
        float xnA = (t + 1 < S_LEN) ? xrA[(size_t)(t + 1) * GDIM] : 0.0f;
        float xnB = (t + 1 < S_LEN) ? xrB[(size_t)(t + 1) * GDIM] : 0.0f;

        const float* hb = sHb + ((t + 1) & 1) * HID;
        const ulonglong2* h4 = (const ulonglong2*)hb;   // 32 chunks of 2 u64

        // ---- dual matvec: h chunks read ONCE, feed both rows ----
        u64 a0 = pk2(xcA + biasA, 0.0f);
        u64 a1 = 0ull, a2 = 0ull, a3 = 0ull;
        u64 e0 = pk2(xcB + biasB, 0.0f);
        u64 e1 = 0ull, e2 = 0ull, e3 = 0ull;
        // cols 0..31: A from regs, B from regs
#pragma unroll
        for (int q = 0; q < 8; q++) {
            ulonglong2 h2 = h4[q];               // cols 4q..4q+3
            a0 = ffma2(wA[2 * q],     h2.x, a0);
            a1 = ffma2(wA[2 * q + 1], h2.y, a1);
            e0 = ffma2(wB[2 * q],     h2.x, e0);
            e1 = ffma2(wB[2 * q + 1], h2.y, e1);
        }
        // cols 32..127: A from regs, B from SMEM
#pragma unroll
        for (int q = 0; q < 24; q++) {
            ulonglong2 h2 = h4[8 + q];
            ulonglong2 b2 = pB[q];
            a2 = ffma2(wA[16 + 2 * q],     h2.x, a2);
            a3 = ffma2(wA[16 + 2 * q + 1], h2.y, a3);
            e2 = ffma2(b2.x, h2.x, e2);
            e3 = ffma2(b2.y, h2.y, e3);
        }
        float2 p0 = upk2(a0), p1 = upk2(a1), p2 = upk2(a2), p3 = upk2(a3);
        float rawA = ((p0.x + p0.y) + (p1.x + p1.y)) + ((p2.x + p2.y) + (p3.x + p3.y));
        float2 q0 = upk2(e0), q1 = upk2(e1), q2 = upk2(e2), q3 = upk2(e3);
        float rawB = ((q0.x + q0.y) + (q1.x + q1.y)) + ((q2.x + q2.y) + (q3.x + q3.y));

        sG[rowA] = sigf(rawA);                            // i/f: sigmoid
        sG[rowB] = tanhB ? tanh_f(rawB) : sigf(rawB);     // g: tanh, o: sigmoid
        __syncthreads();   // bar#1: all 512 gates visible; all h reads done

        // ---- cell/hidden update: h-idx = tid for tid<128 (warps 0-3) ----
        const int wbuf = t & 1;
        if (tid < HID) {
            float iv = sG[tid], fv = sG[tid + 128], gv = sG[tid + 256], ov = sG[tid + 384];
            c = fv * c + iv * gv;
            float h = ov * tanh_f(c);
            hlast = h;
            sHb[wbuf * HID + tid] = h;
            orow[(size_t)t * HID + tid] = h;
        }
        __syncthreads();   // bar#2: new h visible for next step's matvec
        xcA = xnA;
        xcB = xnB;
    }

    if (tid < HID) hT[b * HID + tid] = hlast;
}

// ---------------------------------------------------------------------------
// Launch: per layer, GEMM (xg precompute) then recurrent scan.
// ---------------------------------------------------------------------------
extern "C" void kernel_launch(void* const* d_in, const int* in_sizes, int n_in,
                              void* d_out, int out_size)
{
    const float* x    = (const float*)d_in[0];  // (64,2048,64)
    const float* h0   = (const float*)d_in[1];  // (6,64,128)
    const float* c0   = (const float*)d_in[2];  // (6,64,128)
    const float* Wih0 = (const float*)d_in[3];  // (512,64)
    const float* WihR = (const float*)d_in[4];  // (5,512,128)
    const float* Whh  = (const float*)d_in[5];  // (6,512,128)
    const float* bih  = (const float*)d_in[6];  // (6,512)
    const float* bhh  = (const float*)d_in[7];  // (6,512)
    float* out = (float*)d_out;                 // (6,64,128)

    const int GEMM_SMEM = 2 * 128 * 68 * 4;     // 69,632 B
    cudaFuncSetAttribute(gemm_xg<64>,  cudaFuncAttributeMaxDynamicSharedMemorySize, GEMM_SMEM);
    cudaFuncSetAttribute(gemm_xg<128>, cudaFuncAttributeMaxDynamicSharedMemorySize, GEMM_SMEM);
    cudaFuncSetAttribute(lstm_recur1,  cudaFuncAttributeMaxDynamicSharedMemorySize, RECUR_SMEM);

    dim3 ggrid(4, 1024);   // N-tiles x M-tiles

    // layer 0: input x (K=64), recur writes g_seq0 (osel=1)
    gemm_xg<64><<<ggrid, 256, GEMM_SMEM>>>(x, Wih0, 0);
    lstm_recur1<<<BATCH, 256, RECUR_SMEM>>>(Whh, h0, c0, bih, bhh, 1, out);

    int insel = 1;
    for (int l = 1; l < NL; l++) {
        int outsel = (insel == 1) ? 2 : 1;
        gemm_xg<128><<<ggrid, 256, GEMM_SMEM>>>(
            nullptr, WihR + (size_t)(l - 1) * GDIM * HID, insel);
        lstm_recur1<<<BATCH, 256, RECUR_SMEM>>>(
            Whh + (size_t)l * GDIM * HID,
            h0 + l * BATCH * HID,
            c0 + l * BATCH * HID,
            bih + l * GDIM,
            bhh + l * GDIM,
            outsel,
            out + l * BATCH * HID);
        insel = outsel;
    }
}

// round 17
// speedup vs baseline: 1.6914x; 1.1033x over previous
#include <cuda_runtime.h>
#include <cstddef>

// ---------------------------------------------------------------------------
// Problem constants (fixed by the dataset)
// ---------------------------------------------------------------------------
#define S_LEN 2048
#define BATCH 64
#define IN0   64
#define HID   128
#define GDIM  512          // 4*HID, PyTorch gate order: i, f, g, o
#define NL    6
#define MROWS (BATCH * S_LEN)   // 131072

// ---------------------------------------------------------------------------
// Static device scratch (no allocation allowed)
// ---------------------------------------------------------------------------
__device__ float g_xg  [(size_t)MROWS * GDIM];  // 256 MB: per-layer xg = seq @ Wih^T
__device__ float g_seq0[(size_t)MROWS * HID];   // 64 MB ping
__device__ float g_seq1[(size_t)MROWS * HID];   // 64 MB pong

typedef unsigned long long u64;

// ---------------------------------------------------------------------------
// f32x2 helpers (sm_103a packed fp32 pipe)
// ---------------------------------------------------------------------------
__device__ __forceinline__ u64 pk2(float a, float b) {
    u64 r;
    unsigned ua = __float_as_uint(a), ub = __float_as_uint(b);
    asm("mov.b64 %0, {%1, %2};" : "=l"(r) : "r"(ua), "r"(ub));
    return r;
}
__device__ __forceinline__ u64 ffma2(u64 a, u64 b, u64 c) {
    u64 d;
    asm("fma.rn.f32x2 %0, %1, %2, %3;" : "=l"(d) : "l"(a), "l"(b), "l"(c));
    return d;
}
__device__ __forceinline__ float2 upk2(u64 v) {
    unsigned lo, hi;
    asm("mov.b64 {%0, %1}, %2;" : "=r"(lo), "=r"(hi) : "l"(v));
    return make_float2(__uint_as_float(lo), __uint_as_float(hi));
}

// Fast sigmoid/tanh: __fdividef -> single MUFU.RCP (lat 16, err ~2^-21)
// instead of nvcc's default IEEE division subroutine (~10 inst + 2 MUFU,
// ~60-100 cyc serial). The update-tail tanh sits on the step critical path.
__device__ __forceinline__ float sigf(float x) {
    return __fdividef(1.0f, 1.0f + __expf(-x));
}
__device__ __forceinline__ float tanh_f(float x) { return 2.0f * sigf(2.0f * x) - 1.0f; }

// ---------------------------------------------------------------------------
// GEMM: g_xg[r][n] = sum_k A[r][k] * W[n][k]   (unchanged from round 6)
// ---------------------------------------------------------------------------
template<int K>
__global__ __launch_bounds__(256, 1)
void gemm_xg(const float* __restrict__ Ax, const float* __restrict__ W, int asel)
{
    const float* A = (asel == 1) ? g_seq0 : (asel == 2) ? g_seq1 : Ax;
    extern __shared__ float sm[];
    float* As = sm;             // 128 x 68
    float* Bs = sm + 128 * 68;  // 128 x 68
    const int tx = threadIdx.x & 15;
    const int ty = threadIdx.x >> 4;
    const int row0 = blockIdx.y * 128;
    const int col0 = blockIdx.x * 128;

    u64 acc2[8][8];
#pragma unroll
    for (int i = 0; i < 8; i++)
#pragma unroll
        for (int j = 0; j < 8; j++) acc2[i][j] = 0ull;

    const int NCH = K / 64;
    for (int kc = 0; kc < NCH; kc++) {
        if (kc) __syncthreads();
#pragma unroll
        for (int p = 0; p < 8; p++) {
            int idx = threadIdx.x + 256 * p;
            int r = idx >> 4;
            int q = idx & 15;
            float4 av = *(const float4*)(A + (size_t)(row0 + r) * K + kc * 64 + 4 * q);
            *(float4*)(As + r * 68 + 4 * q) = av;
            float4 wv = *(const float4*)(W + (size_t)(col0 + r) * K + kc * 64 + 4 * q);
            *(float4*)(Bs + r * 68 + 4 * q) = wv;
        }
        __syncthreads();

        const ulonglong2* As2 = (const ulonglong2*)As;
        const ulonglong2* Bs2 = (const ulonglong2*)Bs;
        for (int kq = 0; kq < 16; kq++) {
            ulonglong2 b2[8];
#pragma unroll
            for (int j = 0; j < 8; j++) b2[j] = Bs2[(tx + 16 * j) * 17 + kq];
#pragma unroll
            for (int i = 0; i < 8; i++) {
                ulonglong2 a2 = As2[(ty + 16 * i) * 17 + kq];
#pragma unroll
                for (int j = 0; j < 8; j++) {
                    acc2[i][j] = ffma2(a2.x, b2[j].x, acc2[i][j]);
                    acc2[i][j] = ffma2(a2.y, b2[j].y, acc2[i][j]);
                }
            }
        }
    }

#pragma unroll
    for (int i = 0; i < 8; i++) {
        size_t rbase = (size_t)(row0 + ty + 16 * i) * GDIM + col0 + tx;
#pragma unroll
        for (int j = 0; j < 8; j++) {
            float2 p = upk2(acc2[i][j]);
            g_xg[rbase + 16 * j] = p.x + p.y;
        }
    }
}

// ---------------------------------------------------------------------------
// Recurrent kernel: SINGLE CTA PER BATCH ROW (round-16 best, unchanged
// except fast-division activations).
//   256 threads; thread tid owns TWO gate rows:
//     row A = tid        (gates i/f; sigmoid)
//     row B = tid + 256  (gates g/o; tanh for warps 0-3, sigmoid 4-7)
//   Weight residency: row A fully in regs (64 u64); row B cols 0-31 in regs
//   (16 u64), cols 32-127 in SMEM (256 x 100-float padded, conflict-free
//   LDS.128). Per step: 128 ffma2, 32 broadcast h-LDS.128, 24 B-LDS.128,
//   act, bar#1, update (tid<128), bar#2.
// ---------------------------------------------------------------------------
#define WB_STRIDE 100    // floats per SMEM B-row (96 data + 4 pad)
#define RECUR_SMEM ((256 * WB_STRIDE + 2 * HID + GDIM + 8) * 4)

__global__ __launch_bounds__(256, 1)
void lstm_recur1(const float* __restrict__ Whh,   // (512,128) this layer
                 const float* __restrict__ h0,    // (64,128)
                 const float* __restrict__ c0,    // (64,128)
                 const float* __restrict__ bih,   // (512)
                 const float* __restrict__ bhh,   // (512)
                 int osel,                        // 1 -> g_seq0, 2 -> g_seq1
                 float* __restrict__ hT)          // (64,128) slice of output
{
    extern __shared__ float smem[];
    float* sWB = smem;                          // 256 x 100 (B cols 32..127)
    float* sHb = smem + 256 * WB_STRIDE;        // 2 x 128 (double-buffered h)
    float* sG  = sHb + 2 * HID;                 // 512 activated gates

    const int tid = threadIdx.x;
    const int b = blockIdx.x;                   // batch row
    const int rowA = tid;                       // i/f gates
    const int rowB = tid + 256;                 // g/o gates
    float* seq_out = (osel == 1) ? g_seq0 : g_seq1;

    // ---- row A weights: 128 cols into 64 u64 regs ----
    u64 wA[64];
    {
        const float* wr = Whh + (size_t)rowA * HID;
#pragma unroll
        for (int q = 0; q < 32; q++) {
            float4 v = *(const float4*)(wr + 4 * q);
            wA[2 * q]     = pk2(v.x, v.y);
            wA[2 * q + 1] = pk2(v.z, v.w);
        }
    }
    // ---- row B weights: cols 0..31 into 16 u64 regs, cols 32..127 to SMEM --
    u64 wB[16];
    {
        const float* wr = Whh + (size_t)rowB * HID;
#pragma unroll
        for (int q = 0; q < 8; q++) {
            float4 v = *(const float4*)(wr + 4 * q);
            wB[2 * q]     = pk2(v.x, v.y);
            wB[2 * q + 1] = pk2(v.z, v.w);
        }
        float* dst = sWB + tid * WB_STRIDE;
#pragma unroll
        for (int q = 0; q < 24; q++)
            *(float4*)(dst + 4 * q) = *(const float4*)(wr + 32 + 4 * q);
    }
    const float biasA = bih[rowA] + bhh[rowA];
    const float biasB = bih[rowB] + bhh[rowB];
    const bool tanhB = (tid < 128);             // rowB in [256,384) = g gate

    // ---- init: h0 into buffer 1 (read by step 0), c in updater regs ----
    if (tid < HID) sHb[HID + tid] = h0[b * HID + tid];
    float c = 0.0f, hlast = 0.0f;
    if (tid < HID) c = c0[b * HID + tid];
    __syncthreads();

    const float* xrA = g_xg + ((size_t)b * S_LEN) * GDIM + rowA;
    const float* xrB = g_xg + ((size_t)b * S_LEN) * GDIM + rowB;
    float* orow = seq_out + ((size_t)b * S_LEN) * HID;
    const ulonglong2* pB = (const ulonglong2*)(sWB + tid * WB_STRIDE);

    float xcA = xrA[0];
    float xcB = xrB[0];
    for (int t = 0; t < S_LEN; t++) {
        float xnA = (t + 1 < S_LEN) ? xrA[(size_t)(t + 1) * GDIM] : 0.0f;
        float xnB = (t + 1 < S_LEN) ? xrB[(size_t)(t + 1) * GDIM] : 0.0f;

        const float* hb = sHb + ((t + 1) & 1) * HID;
        const ulonglong2* h4 = (const ulonglong2*)hb;   // 32 chunks of 2 u64

        // ---- dual matvec: h chunks read ONCE, feed both rows ----
        u64 a0 = pk2(xcA + biasA, 0.0f);
        u64 a1 = 0ull, a2 = 0ull, a3 = 0ull;
        u64 e0 = pk2(xcB + biasB, 0.0f);
        u64 e1 = 0ull, e2 = 0ull, e3 = 0ull;
        // cols 0..31: A from regs, B from regs
#pragma unroll
        for (int q = 0; q < 8; q++) {
            ulonglong2 h2 = h4[q];               // cols 4q..4q+3
            a0 = ffma2(wA[2 * q],     h2.x, a0);
            a1 = ffma2(wA[2 * q + 1], h2.y, a1);
            e0 = ffma2(wB[2 * q],     h2.x, e0);
            e1 = ffma2(wB[2 * q + 1], h2.y, e1);
        }
        // cols 32..127: A from regs, B from SMEM
#pragma unroll
        for (int q = 0; q < 24; q++) {
            ulonglong2 h2 = h4[8 + q];
            ulonglong2 b2 = pB[q];
            a2 = ffma2(wA[16 + 2 * q],     h2.x, a2);
            a3 = ffma2(wA[16 + 2 * q + 1], h2.y, a3);
            e2 = ffma2(b2.x, h2.x, e2);
            e3 = ffma2(b2.y, h2.y, e3);
        }
        float2 p0 = upk2(a0), p1 = upk2(a1), p2 = upk2(a2), p3 = upk2(a3);
        float rawA = ((p0.x + p0.y) + (p1.x + p1.y)) + ((p2.x + p2.y) + (p3.x + p3.y));
        float2 q0 = upk2(e0), q1 = upk2(e1), q2 = upk2(e2), q3 = upk2(e3);
        float rawB = ((q0.x + q0.y) + (q1.x + q1.y)) + ((q2.x + q2.y) + (q3.x + q3.y));

        sG[rowA] = sigf(rawA);                            // i/f: sigmoid
        sG[rowB] = tanhB ? tanh_f(rawB) : sigf(rawB);     // g: tanh, o: sigmoid
        __syncthreads();   // bar#1: all 512 gates visible; all h reads done

        // ---- cell/hidden update: h-idx = tid for tid<128 (warps 0-3) ----
        const int wbuf = t & 1;
        if (tid < HID) {
            float iv = sG[tid], fv = sG[tid + 128], gv = sG[tid + 256], ov = sG[tid + 384];
            c = fv * c + iv * gv;
            float h = ov * tanh_f(c);
            hlast = h;
            sHb[wbuf * HID + tid] = h;
            orow[(size_t)t * HID + tid] = h;
        }
        __syncthreads();   // bar#2: new h visible for next step's matvec
        xcA = xnA;
        xcB = xnB;
    }

    if (tid < HID) hT[b * HID + tid] = hlast;
}

// ---------------------------------------------------------------------------
// Launch: per layer, GEMM (xg precompute) then recurrent scan.
// ---------------------------------------------------------------------------
extern "C" void kernel_launch(void* const* d_in, const int* in_sizes, int n_in,
                              void* d_out, int out_size)
{
    const float* x    = (const float*)d_in[0];  // (64,2048,64)
    const float* h0   = (const float*)d_in[1];  // (6,64,128)
    const float* c0   = (const float*)d_in[2];  // (6,64,128)
    const float* Wih0 = (const float*)d_in[3];  // (512,64)
    const float* WihR = (const float*)d_in[4];  // (5,512,128)
    const float* Whh  = (const float*)d_in[5];  // (6,512,128)
    const float* bih  = (const float*)d_in[6];  // (6,512)
    const float* bhh  = (const float*)d_in[7];  // (6,512)
    float* out = (float*)d_out;                 // (6,64,128)

    const int GEMM_SMEM = 2 * 128 * 68 * 4;     // 69,632 B
    cudaFuncSetAttribute(gemm_xg<64>,  cudaFuncAttributeMaxDynamicSharedMemorySize, GEMM_SMEM);
    cudaFuncSetAttribute(gemm_xg<128>, cudaFuncAttributeMaxDynamicSharedMemorySize, GEMM_SMEM);
    cudaFuncSetAttribute(lstm_recur1,  cudaFuncAttributeMaxDynamicSharedMemorySize, RECUR_SMEM);

    dim3 ggrid(4, 1024);   // N-tiles x M-tiles

    // layer 0: input x (K=64), recur writes g_seq0 (osel=1)
    gemm_xg<64><<<ggrid, 256, GEMM_SMEM>>>(x, Wih0, 0);
    lstm_recur1<<<BATCH, 256, RECUR_SMEM>>>(Whh, h0, c0, bih, bhh, 1, out);

    int insel = 1;
    for (int l = 1; l < NL; l++) {
        int outsel = (insel == 1) ? 2 : 1;
        gemm_xg<128><<<ggrid, 256, GEMM_SMEM>>>(
            nullptr, WihR + (size_t)(l - 1) * GDIM * HID, insel);
        lstm_recur1<<<BATCH, 256, RECUR_SMEM>>>(
            Whh + (size_t)l * GDIM * HID,
            h0 + l * BATCH * HID,
            c0 + l * BATCH * HID,
            bih + l * GDIM,
            bhh + l * GDIM,
            outsel,
            out + l * BATCH * HID);
        insel = outsel;
    }
}